// round 13
// baseline (speedup 1.0000x reference)
#include <cuda_runtime.h>
#include <cuda_bf16.h>
#include <math.h>
#include <stdint.h>

// Problem dims
#define B_  4
#define T_  1024
#define V_  32000
#define D_  384
#define H_  6
#define HS_ 64
#define L_  6
#define DFF_ 1536
#define BT_ (B_*T_)
#define QKVW_ (3*H_*HS_)   // 1152
#define NCH_ (V_/128)      // lsepart capacity
#define EPS_ 1e-5f
#define SCALE_ 0.125f

// ---------------- static scratch ----------------
__device__ float g_x[BT_*D_];
__device__ float g_h[BT_*D_];
__device__ float g_qkv[(size_t)BT_*QKVW_];
__device__ float g_wpack[(size_t)L_*QKVW_*D_];
__device__ float g_woT[(size_t)L_*D_*(H_*HS_)];
__device__ float g_w1T[(size_t)L_*DFF_*D_];
__device__ float g_w2T[(size_t)L_*D_*DFF_];
__device__ float g_wlmT[(size_t)V_*D_];
__device__ float g_vT[(size_t)D_*BT_];
__device__ float g_av[BT_*D_];
__device__ float g_ffn[BT_*DFF_];
__device__ float g_wm[B_*H_*T_];
__device__ float g_sufv[(size_t)B_*H_*T_*HS_];
__device__ float2 g_lsepart[(size_t)BT_*NCH_];
__device__ float g_rowloss[BT_];
__device__ float g_logits[(size_t)BT_*V_];

// ---------------- tf32 helper ----------------
__device__ __forceinline__ float tf32r(float x)
{
    asm("cvt.rna.tf32.f32 %0, %0;" : "+f"(x));
    return x;
}
#define FU(x) __float_as_uint(x)

// ---------------- embed ----------------
__global__ void embed_kernel(const int* __restrict__ tok,
                             const float* __restrict__ tt,
                             const float* __restrict__ pt,
                             float* __restrict__ x)
{
    int idx = blockIdx.x * blockDim.x + threadIdx.x;
    if (idx >= BT_*D_) return;
    int bt = idx / D_;
    int d  = idx - bt * D_;
    int t  = bt % T_;
    x[idx] = tt[(size_t)tok[bt] * D_ + d] + pt[t * D_ + d];
}

// ---------------- tiled transpose ----------------
__global__ void transpose_kernel(const float* __restrict__ in,
                                 float* __restrict__ out,
                                 int ldi, int ldo, int zdiv, int roundout,
                                 long long sId, long long sIm,
                                 long long sOd, long long sOm)
{
    __shared__ float tile[32][33];
    int z  = blockIdx.z;
    int zq = z / zdiv;
    int zr = z - zq * zdiv;
    in  += zq * sId + (long long)zr * sIm;
    out += zq * sOd + (long long)zr * sOm;

    int r0 = blockIdx.y * 32;
    int c0 = blockIdx.x * 32;
    int tx = threadIdx.x, ty = threadIdx.y;
    #pragma unroll
    for (int j = 0; j < 4; j++)
        tile[ty + 8*j][tx] = in[(size_t)(r0 + ty + 8*j) * ldi + c0 + tx];
    __syncthreads();
    #pragma unroll
    for (int j = 0; j < 4; j++) {
        float v = tile[tx][ty + 8*j];
        if (roundout) v = tf32r(v);
        out[(size_t)(c0 + ty + 8*j) * ldo + r0 + tx] = v;
    }
}

// ---------------- layernorm ----------------
__global__ void ln_kernel(const float* __restrict__ x,
                          const float* __restrict__ g,
                          const float* __restrict__ b,
                          float* __restrict__ y)
{
    __shared__ float rs[128], rq[128];
    int row = blockIdx.x;
    int tid = threadIdx.x;
    const float* xr = x + (size_t)row * D_;
    float s = 0.f, q = 0.f;
    #pragma unroll
    for (int i = tid; i < D_; i += 128) { float v = xr[i]; s += v; q += v*v; }
    rs[tid] = s; rq[tid] = q;
    __syncthreads();
    for (int off = 64; off > 0; off >>= 1) {
        if (tid < off) { rs[tid] += rs[tid+off]; rq[tid] += rq[tid+off]; }
        __syncthreads();
    }
    float mean = rs[0] / D_;
    float var  = rq[0] / D_ - mean * mean;
    float inv  = rsqrtf(var + EPS_);
    float* yr = y + (size_t)row * D_;
    #pragma unroll
    for (int i = tid; i < D_; i += 128)
        yr[i] = tf32r((xr[i] - mean) * inv * g[i] + b[i]);
}

__device__ __forceinline__ void mma_tf32(float c[4],
    uint32_t a0, uint32_t a1, uint32_t a2, uint32_t a3,
    uint32_t b0, uint32_t b1)
{
    asm volatile(
        "mma.sync.aligned.m16n8k8.row.col.f32.tf32.tf32.f32 "
        "{%0,%1,%2,%3}, {%4,%5,%6,%7}, {%8,%9}, {%0,%1,%2,%3};"
        : "+f"(c[0]), "+f"(c[1]), "+f"(c[2]), "+f"(c[3])
        : "r"(a0), "r"(a1), "r"(a2), "r"(a3), "r"(b0), "r"(b1));
}

// ---------------- NT tensor-core GEMM, cp.async 3-stage (static smem, occ 2) ----
template<int BM, int BN, int WM, int WN>
__global__ void __launch_bounds__(256, 2)
ntgemm_kernel(const float* __restrict__ A,
              const float* __restrict__ B,
              float* __restrict__ C,
              const float* __restrict__ bias,
              int K, int lda, int ldb, int ldc,
              int accumulate, int relu, int roundout,
              float2* lsepart, int zdiv,
              long long sAd, long long sAm,
              long long sBd, long long sBm,
              long long sCd, long long sCm)
{
    constexpr int BK = 16;
    constexpr int NSTAGE = 3;
    constexpr int MT = WM / 16;
    constexpr int NT = WN / 8;
    constexpr int WARPS_N = BN / WN;
    static_assert((BM/WM) * (BN/WN) == 8, "8 warps");
    constexpr int APT = BM / 64;
    constexpr int BPT = BN / 64;

    __shared__ float As[NSTAGE][BM][BK];
    __shared__ float Bs[NSTAGE][BN][BK];

    const int row0 = blockIdx.y * BM;
    const int col0 = blockIdx.x * BN;

    int z  = blockIdx.z;
    int zq = z / zdiv;
    int zr = z - zq * zdiv;
    A += zq * sAd + (long long)zr * sAm;
    B += zq * sBd + (long long)zr * sBm;
    C += zq * sCd + (long long)zr * sCm;

    const int tid  = threadIdx.x;
    const int lane = tid & 31;
    const int wid  = tid >> 5;
    const int wm   = wid / WARPS_N;
    const int wn   = wid % WARPS_N;
    const int gid  = lane >> 2;
    const int tig4 = (lane & 3) * 4;

    float acc[MT][NT][4] = {};

    const int s_row = tid >> 2;
    const int s_kq  = (tid & 3) * 4;

    auto ISSUE = [&](int stage, int k0) {
        if (k0 < K) {
            #pragma unroll
            for (int i = 0; i < APT; i++) {
                uint32_t dst = (uint32_t)__cvta_generic_to_shared(&As[stage][s_row + i*64][s_kq]);
                const float* src = A + (size_t)(row0 + s_row + i*64) * lda + k0 + s_kq;
                asm volatile("cp.async.cg.shared.global [%0], [%1], 16;\n" :: "r"(dst), "l"(src));
            }
            #pragma unroll
            for (int i = 0; i < BPT; i++) {
                uint32_t dst = (uint32_t)__cvta_generic_to_shared(&Bs[stage][s_row + i*64][s_kq]);
                const float* src = B + (size_t)(col0 + s_row + i*64) * ldb + k0 + s_kq;
                asm volatile("cp.async.cg.shared.global [%0], [%1], 16;\n" :: "r"(dst), "l"(src));
            }
        }
        asm volatile("cp.async.commit_group;\n");
    };

    auto COMPUTE = [&](int buf) {
        float4 bq[NT];
        #pragma unroll
        for (int nt = 0; nt < NT; nt++)
            bq[nt] = *(const float4*)&Bs[buf][wn*WN + nt*8 + gid][tig4];
        #pragma unroll
        for (int mt = 0; mt < MT; mt++) {
            int m0 = wm*WM + mt*16 + gid;
            float4 a0 = *(const float4*)&As[buf][m0    ][tig4];
            float4 a1 = *(const float4*)&As[buf][m0 + 8][tig4];
            #pragma unroll
            for (int nt = 0; nt < NT; nt++) {
                mma_tf32(acc[mt][nt], FU(a0.x), FU(a1.x), FU(a0.y), FU(a1.y),
                         FU(bq[nt].x), FU(bq[nt].y));
                mma_tf32(acc[mt][nt], FU(a0.z), FU(a1.z), FU(a0.w), FU(a1.w),
                         FU(bq[nt].z), FU(bq[nt].w));
            }
        }
    };

    ISSUE(0, 0);
    ISSUE(1, BK);

    const int niter = K / BK;
    for (int it = 0; it < niter; it++) {
        asm volatile("cp.async.wait_group 1;\n");
        __syncthreads();
        ISSUE((it + NSTAGE - 1) % NSTAGE, (it + NSTAGE - 1) * BK);
        COMPUTE(it % NSTAGE);
    }

    if (lsepart) {
        asm volatile("cp.async.wait_group 0;\n");
        __syncthreads();
        float2* lse_s = (float2*)&As[0][0][0];
        #pragma unroll
        for (int mt = 0; mt < MT; mt++) {
            float va[2][NT*2];
            #pragma unroll
            for (int nt = 0; nt < NT; nt++) {
                int r = row0 + wm*WM + mt*16 + gid;
                int c = col0 + wn*WN + nt*8 + (lane & 3)*2;
                float2 v0 = make_float2(acc[mt][nt][0], acc[mt][nt][1]);
                float2 v1 = make_float2(acc[mt][nt][2], acc[mt][nt][3]);
                if (bias) {
                    float2 bb = *(const float2*)(bias + c);
                    v0.x += bb.x; v0.y += bb.y;
                    v1.x += bb.x; v1.y += bb.y;
                }
                *(float2*)(C + (size_t)r * ldc + c)     = v0;
                *(float2*)(C + (size_t)(r+8) * ldc + c) = v1;
                va[0][nt*2] = v0.x; va[0][nt*2+1] = v0.y;
                va[1][nt*2] = v1.x; va[1][nt*2+1] = v1.y;
            }
            #pragma unroll
            for (int hf = 0; hf < 2; hf++) {
                float mx = va[hf][0];
                #pragma unroll
                for (int j = 1; j < NT*2; j++) mx = fmaxf(mx, va[hf][j]);
                float sm = 0.f;
                #pragma unroll
                for (int j = 0; j < NT*2; j++) sm += __expf(va[hf][j] - mx);
                #pragma unroll
                for (int off = 1; off <= 2; off <<= 1) {
                    float mo = __shfl_xor_sync(0xffffffffu, mx, off);
                    float so = __shfl_xor_sync(0xffffffffu, sm, off);
                    float M = fmaxf(mx, mo);
                    sm = sm*__expf(mx - M) + so*__expf(mo - M);
                    mx = M;
                }
                if ((lane & 3) == 0) {
                    int rl = wm*WM + mt*16 + gid + hf*8;
                    lse_s[rl*WARPS_N + wn] = make_float2(mx, sm);
                }
            }
        }
        __syncthreads();
        if (tid < BM) {
            float2 a = lse_s[tid*WARPS_N];
            #pragma unroll
            for (int w = 1; w < WARPS_N; w++) {
                float2 b = lse_s[tid*WARPS_N + w];
                float M = fmaxf(a.x, b.x);
                a = make_float2(M, a.y*__expf(a.x - M) + b.y*__expf(b.x - M));
            }
            lsepart[(size_t)(row0 + tid) * gridDim.x + blockIdx.x] = a;
        }
        return;
    }

    #pragma unroll
    for (int mt = 0; mt < MT; mt++) {
        #pragma unroll
        for (int nt = 0; nt < NT; nt++) {
            int r = row0 + wm*WM + mt*16 + gid;
            int c = col0 + wn*WN + nt*8 + (lane & 3)*2;
            float2 v0 = make_float2(acc[mt][nt][0], acc[mt][nt][1]);
            float2 v1 = make_float2(acc[mt][nt][2], acc[mt][nt][3]);
            if (bias) {
                float2 bb = *(const float2*)(bias + c);
                v0.x += bb.x; v0.y += bb.y;
                v1.x += bb.x; v1.y += bb.y;
            }
            float* p0 = C + (size_t)r * ldc + c;
            float* p1 = C + (size_t)(r+8) * ldc + c;
            if (accumulate) {
                float2 c0 = *(const float2*)p0;
                float2 c1 = *(const float2*)p1;
                v0.x += c0.x; v0.y += c0.y;
                v1.x += c1.x; v1.y += c1.y;
            }
            if (relu) {
                v0.x = fmaxf(v0.x, 0.f); v0.y = fmaxf(v0.y, 0.f);
                v1.x = fmaxf(v1.x, 0.f); v1.y = fmaxf(v1.y, 0.f);
            }
            if (roundout) {
                v0.x = tf32r(v0.x); v0.y = tf32r(v0.y);
                v1.x = tf32r(v1.x); v1.y = tf32r(v1.y);
            }
            *(float2*)p0 = v0;
            *(float2*)p1 = v1;
        }
    }
}

// ---------------- fused attention (scores + online softmax quirk + AV) -----------
#define AT_SMEM ((128*64 + 64*64 + 64*64 + 128*64 + 256 + 256)*4)

__global__ void __launch_bounds__(256, 2)
attn_kernel(const float* __restrict__ qkv,
            const float* __restrict__ vT,
            float* __restrict__ av,
            float* __restrict__ wmout)
{
    extern __shared__ float sm[];
    float* Qs   = sm;
    float* Ks   = Qs + 128*64;
    float* Vs   = Ks + 64*64;
    float* Ps   = Vs + 64*64;
    float* rmax = Ps + 128*64;
    float* rsum = rmax + 256;

    const int bh = blockIdx.x;
    const int b = bh / H_, h = bh - b*H_;
    const int row0 = (gridDim.y - 1 - blockIdx.y) * 128;

    const int tid  = threadIdx.x;
    const int lane = tid & 31;
    const int wid  = tid >> 5;
    const int wm   = wid >> 1;
    const int wn   = wid & 1;
    const int gid  = lane >> 2;
    const int tig  = lane & 3;

    {
        const float* qbase = qkv + (size_t)(b*T_ + row0) * QKVW_ + h*HS_;
        #pragma unroll
        for (int i = 0; i < 8; i++) {
            int idx = tid + i*256;
            int r = idx >> 4, c = idx & 15;
            int cc = (c + ((r & 3) << 2)) & 15;
            uint32_t dst = (uint32_t)__cvta_generic_to_shared(Qs + r*64 + cc*4);
            const float* src = qbase + (size_t)r * QKVW_ + c*4;
            asm volatile("cp.async.cg.shared.global [%0], [%1], 16;\n" :: "r"(dst), "l"(src));
        }
        asm volatile("cp.async.commit_group;\n");
    }

    float m_run[2][2], s_run[2][2];
    float acc_o[2][4][4] = {};
    #pragma unroll
    for (int mt = 0; mt < 2; mt++)
        #pragma unroll
        for (int k = 0; k < 2; k++) { m_run[mt][k] = -1e30f; s_run[mt][k] = 0.f; }

    const int jmax = row0/64 + 2;

    for (int j = 0; j < jmax; j++) {
        __syncthreads();
        {
            const float* kbase = qkv + (size_t)(b*T_ + j*64) * QKVW_ + H_*HS_ + h*HS_;
            const float* vbase = vT + (size_t)(h*HS_) * BT_ + b*T_ + j*64;
            #pragma unroll
            for (int i = 0; i < 4; i++) {
                int idx = tid + i*256;
                int r = idx >> 4, c = idx & 15;
                int cc = (c + ((r & 3) << 2)) & 15;
                uint32_t dk = (uint32_t)__cvta_generic_to_shared(Ks + r*64 + cc*4);
                uint32_t dv = (uint32_t)__cvta_generic_to_shared(Vs + r*64 + cc*4);
                const float* sk = kbase + (size_t)r * QKVW_ + c*4;
                const float* sv = vbase + (size_t)r * BT_ + c*4;
                asm volatile("cp.async.cg.shared.global [%0], [%1], 16;\n" :: "r"(dk), "l"(sk));
                asm volatile("cp.async.cg.shared.global [%0], [%1], 16;\n" :: "r"(dv), "l"(sv));
            }
            asm volatile("cp.async.commit_group;\n");
            asm volatile("cp.async.wait_group 0;\n");
        }
        __syncthreads();

        float acc_s[2][4][4] = {};
        #pragma unroll
        for (int ks = 0; ks < 4; ks++) {
            int fidx = ((ks*16 + tig*4) + ((gid & 3) << 4)) & 63;
            float4 bq[4];
            #pragma unroll
            for (int nt = 0; nt < 4; nt++) {
                int n0 = wn*32 + nt*8 + gid;
                bq[nt] = *(const float4*)&Ks[n0*64 + fidx];
            }
            #pragma unroll
            for (int mt = 0; mt < 2; mt++) {
                int m0 = wm*32 + mt*16 + gid;
                float4 a0 = *(const float4*)&Qs[m0*64 + fidx];
                float4 a1 = *(const float4*)&Qs[(m0+8)*64 + fidx];
                #pragma unroll
                for (int nt = 0; nt < 4; nt++) {
                    mma_tf32(acc_s[mt][nt], FU(a0.x), FU(a1.x), FU(a0.y), FU(a1.y),
                             FU(bq[nt].x), FU(bq[nt].y));
                    mma_tf32(acc_s[mt][nt], FU(a0.z), FU(a1.z), FU(a0.w), FU(a1.w),
                             FU(bq[nt].z), FU(bq[nt].w));
                }
            }
        }

        float tmax[2][2];
        #pragma unroll
        for (int mt = 0; mt < 2; mt++) {
            int t0 = row0 + wm*32 + mt*16 + gid;
            int t1 = t0 + 8;
            tmax[mt][0] = -1e30f; tmax[mt][1] = -1e30f;
            #pragma unroll
            for (int nt = 0; nt < 4; nt++) {
                int c0 = j*64 + wn*32 + nt*8 + tig*2;
                float* a = acc_s[mt][nt];
                a[0] = (c0   <= t0) ? a[0]*SCALE_ : -1e30f;
                a[1] = (c0+1 <= t0) ? a[1]*SCALE_ : -1e30f;
                a[2] = (c0   <= t1) ? a[2]*SCALE_ : -1e30f;
                a[3] = (c0+1 <= t1) ? a[3]*SCALE_ : -1e30f;
                tmax[mt][0] = fmaxf(tmax[mt][0], fmaxf(a[0], a[1]));
                tmax[mt][1] = fmaxf(tmax[mt][1], fmaxf(a[2], a[3]));
            }
            #pragma unroll
            for (int off = 1; off <= 2; off <<= 1) {
                tmax[mt][0] = fmaxf(tmax[mt][0], __shfl_xor_sync(0xffffffffu, tmax[mt][0], off));
                tmax[mt][1] = fmaxf(tmax[mt][1], __shfl_xor_sync(0xffffffffu, tmax[mt][1], off));
            }
            if (tig == 0) {
                int rl = wm*32 + mt*16 + gid;
                rmax[rl*2 + wn]     = tmax[mt][0];
                rmax[(rl+8)*2 + wn] = tmax[mt][1];
            }
        }
        __syncthreads();

        float alpha[2][2], psum[2][2];
        #pragma unroll
        for (int mt = 0; mt < 2; mt++) {
            #pragma unroll
            for (int k = 0; k < 2; k++) {
                int rl = wm*32 + mt*16 + gid + k*8;
                float tm = fmaxf(rmax[rl*2], rmax[rl*2+1]);
                float mn = fmaxf(m_run[mt][k], tm);
                alpha[mt][k] = __expf(m_run[mt][k] - mn);
                m_run[mt][k] = mn;
                psum[mt][k] = 0.f;
            }
        }
        #pragma unroll
        for (int mt = 0; mt < 2; mt++) {
            int r0l = wm*32 + mt*16 + gid;
            int rot = (r0l & 3) << 4;
            #pragma unroll
            for (int nt = 0; nt < 4; nt++) {
                float* a = acc_s[mt][nt];
                float p0 = __expf(a[0] - m_run[mt][0]);
                float p1 = __expf(a[1] - m_run[mt][0]);
                float p2 = __expf(a[2] - m_run[mt][1]);
                float p3 = __expf(a[3] - m_run[mt][1]);
                psum[mt][0] += p0 + p1;
                psum[mt][1] += p2 + p3;
                int c = wn*32 + nt*8 + tig*2;
                int f = (c + rot) & 63;
                *(float2*)&Ps[r0l*64 + f]     = make_float2(tf32r(p0), tf32r(p1));
                *(float2*)&Ps[(r0l+8)*64 + f] = make_float2(tf32r(p2), tf32r(p3));
                float* o = acc_o[mt][nt];
                o[0] *= alpha[mt][0]; o[1] *= alpha[mt][0];
                o[2] *= alpha[mt][1]; o[3] *= alpha[mt][1];
            }
            #pragma unroll
            for (int off = 1; off <= 2; off <<= 1) {
                psum[mt][0] += __shfl_xor_sync(0xffffffffu, psum[mt][0], off);
                psum[mt][1] += __shfl_xor_sync(0xffffffffu, psum[mt][1], off);
            }
            if (tig == 0) {
                rsum[r0l*2 + wn]     = psum[mt][0];
                rsum[(r0l+8)*2 + wn] = psum[mt][1];
            }
        }
        __syncthreads();
        #pragma unroll
        for (int mt = 0; mt < 2; mt++) {
            #pragma unroll
            for (int k = 0; k < 2; k++) {
                int rl = wm*32 + mt*16 + gid + k*8;
                float ts = rsum[rl*2] + rsum[rl*2+1];
                s_run[mt][k] = s_run[mt][k]*alpha[mt][k] + ts;
            }
        }

        #pragma unroll
        for (int ks = 0; ks < 4; ks++) {
            int fidx = ((ks*16 + tig*4) + ((gid & 3) << 4)) & 63;
            float4 bq[4];
            #pragma unroll
            for (int nt = 0; nt < 4; nt++) {
                int e0 = wn*32 + nt*8 + gid;
                bq[nt] = *(const float4*)&Vs[e0*64 + fidx];
            }
            #pragma unroll
            for (int mt = 0; mt < 2; mt++) {
                int m0 = wm*32 + mt*16 + gid;
                float4 a0 = *(const float4*)&Ps[m0*64 + fidx];
                float4 a1 = *(const float4*)&Ps[(m0+8)*64 + fidx];
                #pragma unroll
                for (int nt = 0; nt < 4; nt++) {
                    mma_tf32(acc_o[mt][nt], FU(a0.x), FU(a1.x), FU(a0.y), FU(a1.y),
                             FU(bq[nt].x), FU(bq[nt].y));
                    mma_tf32(acc_o[mt][nt], FU(a0.z), FU(a1.z), FU(a0.w), FU(a1.w),
                             FU(bq[nt].z), FU(bq[nt].w));
                }
            }
        }
    }

    float oscale[2][2];
    #pragma unroll
    for (int mt = 0; mt < 2; mt++) {
        #pragma unroll
        for (int k = 0; k < 2; k++) {
            int t = row0 + wm*32 + mt*16 + gid + k*8;
            float mr = m_run[mt][k], sr = s_run[mt][k];
            int count = T_ - 1 - t;
            float mf = (count > 0) ? fmaxf(mr, 0.f) : mr;
            float emm = __expf(mr - mf);
            float denom = sr * emm + (float)count * __expf(-mf);
            oscale[mt][k] = emm / denom;
            if (wn == 0 && tig == 0)
                wmout[(size_t)bh*T_ + t] = __expf(-mf) / denom;
        }
    }
    #pragma unroll
    for (int mt = 0; mt < 2; mt++) {
        int r = row0 + wm*32 + mt*16 + gid;
        #pragma unroll
        for (int nt = 0; nt < 4; nt++) {
            int c = wn*32 + nt*8 + tig*2;
            float* dst = av + (size_t)(b*T_ + r)*D_ + h*HS_ + c;
            float* o = acc_o[mt][nt];
            *(float2*)dst          = make_float2(o[0]*oscale[mt][0], o[1]*oscale[mt][0]);
            *(float2*)(dst + 8*D_) = make_float2(o[2]*oscale[mt][1], o[3]*oscale[mt][1]);
        }
    }
}

// ---------------- parallel V suffix scan ----------------
__global__ void suffixv_kernel(const float* __restrict__ vT, float* __restrict__ suf)
{
    int gw   = blockIdx.x * 8 + (threadIdx.x >> 5);
    int lane = threadIdx.x & 31;
    int e  = gw >> 2;
    int b  = gw & 3;
    int bh = b * H_ + (e >> 6);
    int ep = e & 63;
    const float* src = vT + (size_t)e * BT_ + b * T_;
    float* dst = suf + (size_t)bh * T_ * HS_ + ep;

    float carry = 0.f;
    for (int j = 31; j >= 0; j--) {
        int t = j*32 + lane;
        float v = src[t];
        float s = v;
        #pragma unroll
        for (int off = 1; off < 32; off <<= 1) {
            float o = __shfl_down_sync(0xffffffffu, s, off);
            if (lane + off < 32) s += o;
        }
        dst[(size_t)t * HS_] = s - v + carry;
        carry += __shfl_sync(0xffffffffu, s, 0);
    }
}

// ---------------- av += wm * SufV, then tf32 round ----------------
__global__ void avcorr_kernel(const float* __restrict__ suf,
                              const float* __restrict__ wm,
                              float* __restrict__ av)
{
    int idx = blockIdx.x * blockDim.x + threadIdx.x;
    if (idx >= BT_*D_/4) return;
    int bt  = idx / (D_/4);
    int rem = idx - bt * (D_/4);
    int h   = rem / (HS_/4);
    int e4  = rem - h * (HS_/4);
    int b = bt / T_, t = bt - b * T_;
    int bh = b*H_ + h;
    float w = wm[(size_t)bh*T_ + t];
    float4 s4 = *(const float4*)&suf[((size_t)bh*T_ + t)*HS_ + e4*4];
    float4 a  = *(float4*)&av[(size_t)bt*D_ + h*HS_ + e4*4];
    a.x = tf32r(fmaf(w, s4.x, a.x));
    a.y = tf32r(fmaf(w, s4.y, a.y));
    a.z = tf32r(fmaf(w, s4.z, a.z));
    a.w = tf32r(fmaf(w, s4.w, a.w));
    *(float4*)&av[(size_t)bt*D_ + h*HS_ + e4*4] = a;
}

// ---------------- loss from LM-head partials ----------------
__global__ void lossrow2_kernel(const float2* __restrict__ part, int nch,
                                const float* __restrict__ logits,
                                const int* __restrict__ tgt,
                                float* __restrict__ rowloss)
{
    int row  = blockIdx.x;
    int lane = threadIdx.x;
    float m = -1e30f, s = 0.f;
    for (int i = lane; i < nch; i += 32) {
        float2 p = part[(size_t)row*nch + i];
        float M = fmaxf(m, p.x);
        s = s*__expf(m - M) + p.y*__expf(p.x - M);
        m = M;
    }
    #pragma unroll
    for (int off = 16; off > 0; off >>= 1) {
        float mo = __shfl_xor_sync(0xffffffffu, m, off);
        float so = __shfl_xor_sync(0xffffffffu, s, off);
        float M = fmaxf(m, mo);
        s = s*__expf(m - M) + so*__expf(mo - M);
        m = M;
    }
    if (lane == 0)
        rowloss[row] = m + logf(s) - logits[(size_t)row*V_ + tgt[row]];
}

__global__ void lossreduce_kernel(const float* __restrict__ rowloss,
                                  float* __restrict__ out)
{
    __shared__ float red[256];
    int tid = threadIdx.x;
    float s = 0.f;
    for (int i = tid; i < BT_; i += 256) s += rowloss[i];
    red[tid] = s; __syncthreads();
    for (int off = 128; off > 0; off >>= 1) {
        if (tid < off) red[tid] += red[tid+off];
        __syncthreads();
    }
    if (tid == 0) out[0] = red[0] / (float)BT_;
}

// ---------------- host ----------------
static float* sym(const void* s)
{
    void* p = nullptr;
    cudaGetSymbolAddress(&p, s);
    return (float*)p;
}

struct GemmArgs {
    const float *A, *B; float* C; const float* bias;
    int M, N, K, lda, ldb, ldc;
    bool acc, relu, round;
    float2* lsepart;
    int Z, zdiv;
    long long sAd, sAm, sBd, sBm, sCd, sCm;
};

static void gemm128x128(const GemmArgs& g)
{
    dim3 grid(g.N / 128, g.M / 128, g.Z);
    ntgemm_kernel<128,128,64,32><<<grid, 256>>>(
        g.A, g.B, g.C, g.bias, g.K, g.lda, g.ldb, g.ldc,
        g.acc, g.relu, g.round, g.lsepart, g.zdiv,
        g.sAd, g.sAm, g.sBd, g.sBm, g.sCd, g.sCm);
}

// 64x128 tile for narrow-N GEMMs (doubles grid parallelism)
static void gemm64x128(const GemmArgs& g)
{
    dim3 grid(g.N / 128, g.M / 64, g.Z);
    ntgemm_kernel<64,128,32,32><<<grid, 256>>>(
        g.A, g.B, g.C, g.bias, g.K, g.lda, g.ldb, g.ldc,
        g.acc, g.relu, g.round, g.lsepart, g.zdiv,
        g.sAd, g.sAm, g.sBd, g.sBm, g.sCd, g.sCm);
}

static void transpose(const float* in, float* out, int R, int C,
                      int ldi, int ldo, int Z, int zdiv, int roundout,
                      long long sId, long long sIm,
                      long long sOd, long long sOm)
{
    dim3 grid(C / 32, R / 32, Z);
    transpose_kernel<<<grid, dim3(32, 8)>>>(in, out, ldi, ldo, zdiv, roundout,
                                            sId, sIm, sOd, sOm);
}

extern "C" void kernel_launch(void* const* d_in, const int* in_sizes, int n_in,
                              void* d_out, int out_size)
{
    const int*   token_ids = (const int*)d_in[0];
    const int*   targets   = (const int*)d_in[1];
    const float* tok_table = (const float*)d_in[2];
    const float* pos_table = (const float*)d_in[3];
    const float* ln1_g = (const float*)d_in[4];
    const float* ln1_b = (const float*)d_in[5];
    const float* Wq = (const float*)d_in[6];
    const float* Wk = (const float*)d_in[7];
    const float* Wv = (const float*)d_in[8];
    const float* Wo = (const float*)d_in[9];
    const float* ln2_g = (const float*)d_in[10];
    const float* ln2_b = (const float*)d_in[11];
    const float* W1 = (const float*)d_in[12];
    const float* b1 = (const float*)d_in[13];
    const float* W2 = (const float*)d_in[14];
    const float* b2 = (const float*)d_in[15];
    const float* lnf_g = (const float*)d_in[16];
    const float* lnf_b = (const float*)d_in[17];
    const float* Wlm = (const float*)d_in[18];
    const float* blm = (const float*)d_in[19];

    cudaFuncSetAttribute(attn_kernel,
                         cudaFuncAttributeMaxDynamicSharedMemorySize, AT_SMEM);

    float* x    = sym(g_x);
    float* h    = sym(g_h);
    float* qkv  = sym(g_qkv);
    float* wp   = sym(g_wpack);
    float* woT  = sym(g_woT);
    float* w1T  = sym(g_w1T);
    float* w2T  = sym(g_w2T);
    float* wlmT = sym(g_wlmT);
    float* vT   = sym(g_vT);
    float* av   = sym(g_av);
    float* ffn  = sym(g_ffn);
    float* wm   = sym(g_wm);
    float* sufv = sym(g_sufv);
    float2* lsp = (float2*)sym(g_lsepart);
    float* rl   = sym(g_rowloss);

    const long long NLOGITS = (long long)BT_ * V_;
    float* out = (float*)d_out;
    bool out_has_logits = ((long long)out_size >= NLOGITS);
    float* logits = out_has_logits ? out : sym(g_logits);

    // ---- embed ----
    embed_kernel<<<(BT_*D_ + 255)/256, 256>>>(token_ids, tok_table, pos_table, x);

    // ---- weight packs ----
    for (int grp = 0; grp < 3; grp++) {
        const float* W = (grp == 0) ? Wq : (grp == 1) ? Wk : Wv;
        transpose(W, wp + (long long)grp*H_*HS_*D_, D_, HS_, HS_, D_,
                  L_*H_, H_, 1,
                  (long long)H_*D_*HS_, (long long)D_*HS_,
                  (long long)QKVW_*D_, (long long)HS_*D_);
    }
    transpose(Wo, woT, H_*HS_, D_, D_, H_*HS_, L_, 1, 1,
              (long long)H_*HS_*D_, 0, (long long)D_*H_*HS_, 0);
    transpose(W1, w1T, D_, DFF_, DFF_, D_, L_, 1, 1,
              (long long)D_*DFF_, 0, (long long)DFF_*D_, 0);
    transpose(W2, w2T, DFF_, D_, D_, DFF_, L_, 1, 1,
              (long long)DFF_*D_, 0, (long long)D_*DFF_, 0);
    transpose(Wlm, wlmT, D_, V_, V_, D_, 1, 1, 1, 0, 0, 0, 0);

    for (int l = 0; l < L_; l++) {
        ln_kernel<<<BT_, 128>>>(x, ln1_g + l*D_, ln1_b + l*D_, h);

        // fused QKV (rounded)
        {
            GemmArgs g{h, wp + (long long)l*QKVW_*D_, qkv, nullptr,
                       BT_, QKVW_, D_, D_, D_, QKVW_,
                       false, false, true, nullptr, 1, 1, 0,0,0,0,0,0};
            gemm128x128(g);
        }

        // V^T, suffix scan
        transpose(qkv + 2*H_*HS_, vT, BT_, D_, QKVW_, BT_, 1, 1, 0, 0, 0, 0, 0);
        suffixv_kernel<<<192, 256>>>(vT, sufv);

        // fused attention
        attn_kernel<<<dim3(B_*H_, T_/128), 256, AT_SMEM>>>(qkv, vT, av, wm);
        avcorr_kernel<<<(BT_*D_/4 + 255)/256, 256>>>(sufv, wm, av);

        // x += av @ Wo[l] — narrow N: 64-row tiles for 2x grid parallelism
        {
            GemmArgs g{av, woT + (long long)l*D_*H_*HS_, x, nullptr,
                       BT_, D_, H_*HS_, H_*HS_, H_*HS_, D_,
                       true, false, false, nullptr, 1, 1, 0,0,0,0,0,0};
            gemm64x128(g);
        }

        ln_kernel<<<BT_, 128>>>(x, ln2_g + l*D_, ln2_b + l*D_, h);

        // ffn1 (wide N: keep 128x128)
        {
            GemmArgs g{h, w1T + (long long)l*DFF_*D_, ffn, b1 + l*DFF_,
                       BT_, DFF_, D_, D_, D_, DFF_,
                       false, true, true, nullptr, 1, 1, 0,0,0,0,0,0};
            gemm128x128(g);
        }
        // ffn2 — narrow N + long K: 64-row tiles
        {
            GemmArgs g{ffn, w2T + (long long)l*D_*DFF_, x, b2 + l*D_,
                       BT_, D_, DFF_, DFF_, DFF_, D_,
                       true, false, false, nullptr, 1, 1, 0,0,0,0,0,0};
            gemm64x128(g);
        }
    }

    ln_kernel<<<BT_, 128>>>(x, lnf_g, lnf_b, h);

    // LM head with fused LSE partials (250 chunks)
    {
        GemmArgs g{h, wlmT, logits, blm,
                   BT_, V_, D_, D_, D_, V_,
                   false, false, false, lsp, 1, 1, 0,0,0,0,0,0};
        gemm128x128(g);
    }

    lossrow2_kernel<<<BT_, 32>>>(lsp, NCH_, logits, targets, rl);
    if (out_has_logits && (long long)out_size > NLOGITS) {
        lossreduce_kernel<<<1, 256>>>(rl, out + NLOGITS);
    } else if (!out_has_logits && out_size >= 1) {
        lossreduce_kernel<<<1, 256>>>(rl, out);
    }
}

// round 14
// speedup vs baseline: 1.5280x; 1.5280x over previous
#include <cuda_runtime.h>
#include <cuda_bf16.h>
#include <math.h>
#include <stdint.h>

// Problem dims
#define B_  4
#define T_  1024
#define V_  32000
#define D_  384
#define H_  6
#define HS_ 64
#define L_  6
#define DFF_ 1536
#define BT_ (B_*T_)
#define QKVW_ (3*H_*HS_)   // 1152
#define NCH_ (V_/128)      // lsepart capacity
#define EPS_ 1e-5f
#define SCALE_ 0.125f

// ---------------- static scratch ----------------
__device__ float g_x[BT_*D_];
__device__ float g_h[BT_*D_];
__device__ float g_qkv[(size_t)BT_*QKVW_];
__device__ float g_wpack[(size_t)L_*QKVW_*D_];
__device__ float g_woT[(size_t)L_*D_*(H_*HS_)];
__device__ float g_w1T[(size_t)L_*DFF_*D_];
__device__ float g_w2T[(size_t)L_*D_*DFF_];
__device__ float g_wlmT[(size_t)V_*D_];
__device__ float g_vT[(size_t)D_*BT_];
__device__ float g_av[BT_*D_];
__device__ float g_ffn[BT_*DFF_];
__device__ float g_sufv[(size_t)B_*H_*T_*HS_];
__device__ float2 g_lsepart[(size_t)BT_*NCH_];
__device__ float g_rowloss[BT_];
__device__ float g_logits[(size_t)BT_*V_];

// ---------------- tf32 helper ----------------
__device__ __forceinline__ float tf32r(float x)
{
    asm("cvt.rna.tf32.f32 %0, %0;" : "+f"(x));
    return x;
}
#define FU(x) __float_as_uint(x)

// ---------------- embed ----------------
__global__ void embed_kernel(const int* __restrict__ tok,
                             const float* __restrict__ tt,
                             const float* __restrict__ pt,
                             float* __restrict__ x)
{
    int idx = blockIdx.x * blockDim.x + threadIdx.x;
    if (idx >= BT_*D_) return;
    int bt = idx / D_;
    int d  = idx - bt * D_;
    int t  = bt % T_;
    x[idx] = tt[(size_t)tok[bt] * D_ + d] + pt[t * D_ + d];
}

// ---------------- tiled transpose ----------------
__global__ void transpose_kernel(const float* __restrict__ in,
                                 float* __restrict__ out,
                                 int ldi, int ldo, int zdiv, int roundout,
                                 long long sId, long long sIm,
                                 long long sOd, long long sOm)
{
    __shared__ float tile[32][33];
    int z  = blockIdx.z;
    int zq = z / zdiv;
    int zr = z - zq * zdiv;
    in  += zq * sId + (long long)zr * sIm;
    out += zq * sOd + (long long)zr * sOm;

    int r0 = blockIdx.y * 32;
    int c0 = blockIdx.x * 32;
    int tx = threadIdx.x, ty = threadIdx.y;
    #pragma unroll
    for (int j = 0; j < 4; j++)
        tile[ty + 8*j][tx] = in[(size_t)(r0 + ty + 8*j) * ldi + c0 + tx];
    __syncthreads();
    #pragma unroll
    for (int j = 0; j < 4; j++) {
        float v = tile[tx][ty + 8*j];
        if (roundout) v = tf32r(v);
        out[(size_t)(c0 + ty + 8*j) * ldo + r0 + tx] = v;
    }
}

// ---------------- layernorm ----------------
__global__ void ln_kernel(const float* __restrict__ x,
                          const float* __restrict__ g,
                          const float* __restrict__ b,
                          float* __restrict__ y)
{
    __shared__ float rs[128], rq[128];
    int row = blockIdx.x;
    int tid = threadIdx.x;
    const float* xr = x + (size_t)row * D_;
    float s = 0.f, q = 0.f;
    #pragma unroll
    for (int i = tid; i < D_; i += 128) { float v = xr[i]; s += v; q += v*v; }
    rs[tid] = s; rq[tid] = q;
    __syncthreads();
    for (int off = 64; off > 0; off >>= 1) {
        if (tid < off) { rs[tid] += rs[tid+off]; rq[tid] += rq[tid+off]; }
        __syncthreads();
    }
    float mean = rs[0] / D_;
    float var  = rq[0] / D_ - mean * mean;
    float inv  = rsqrtf(var + EPS_);
    float* yr = y + (size_t)row * D_;
    #pragma unroll
    for (int i = tid; i < D_; i += 128)
        yr[i] = tf32r((xr[i] - mean) * inv * g[i] + b[i]);
}

__device__ __forceinline__ void mma_tf32(float c[4],
    uint32_t a0, uint32_t a1, uint32_t a2, uint32_t a3,
    uint32_t b0, uint32_t b1)
{
    asm volatile(
        "mma.sync.aligned.m16n8k8.row.col.f32.tf32.tf32.f32 "
        "{%0,%1,%2,%3}, {%4,%5,%6,%7}, {%8,%9}, {%0,%1,%2,%3};"
        : "+f"(c[0]), "+f"(c[1]), "+f"(c[2]), "+f"(c[3])
        : "r"(a0), "r"(a1), "r"(a2), "r"(a3), "r"(b0), "r"(b1));
}

// ---------------- NT tensor-core GEMM, cp.async 3-stage (static smem, occ 2) ----
template<int BM, int BN, int WM, int WN>
__global__ void __launch_bounds__(256, 2)
ntgemm_kernel(const float* __restrict__ A,
              const float* __restrict__ B,
              float* __restrict__ C,
              const float* __restrict__ bias,
              int K, int lda, int ldb, int ldc,
              int accumulate, int relu, int roundout,
              float2* lsepart, int zdiv,
              long long sAd, long long sAm,
              long long sBd, long long sBm,
              long long sCd, long long sCm)
{
    constexpr int BK = 16;
    constexpr int NSTAGE = 3;
    constexpr int MT = WM / 16;
    constexpr int NT = WN / 8;
    constexpr int WARPS_N = BN / WN;
    static_assert((BM/WM) * (BN/WN) == 8, "8 warps");
    constexpr int APT = BM / 64;
    constexpr int BPT = BN / 64;

    __shared__ float As[NSTAGE][BM][BK];
    __shared__ float Bs[NSTAGE][BN][BK];

    const int row0 = blockIdx.y * BM;
    const int col0 = blockIdx.x * BN;

    int z  = blockIdx.z;
    int zq = z / zdiv;
    int zr = z - zq * zdiv;
    A += zq * sAd + (long long)zr * sAm;
    B += zq * sBd + (long long)zr * sBm;
    C += zq * sCd + (long long)zr * sCm;

    const int tid  = threadIdx.x;
    const int lane = tid & 31;
    const int wid  = tid >> 5;
    const int wm   = wid / WARPS_N;
    const int wn   = wid % WARPS_N;
    const int gid  = lane >> 2;
    const int tig4 = (lane & 3) * 4;

    float acc[MT][NT][4] = {};

    const int s_row = tid >> 2;
    const int s_kq  = (tid & 3) * 4;

    auto ISSUE = [&](int stage, int k0) {
        if (k0 < K) {
            #pragma unroll
            for (int i = 0; i < APT; i++) {
                uint32_t dst = (uint32_t)__cvta_generic_to_shared(&As[stage][s_row + i*64][s_kq]);
                const float* src = A + (size_t)(row0 + s_row + i*64) * lda + k0 + s_kq;
                asm volatile("cp.async.cg.shared.global [%0], [%1], 16;\n" :: "r"(dst), "l"(src));
            }
            #pragma unroll
            for (int i = 0; i < BPT; i++) {
                uint32_t dst = (uint32_t)__cvta_generic_to_shared(&Bs[stage][s_row + i*64][s_kq]);
                const float* src = B + (size_t)(col0 + s_row + i*64) * ldb + k0 + s_kq;
                asm volatile("cp.async.cg.shared.global [%0], [%1], 16;\n" :: "r"(dst), "l"(src));
            }
        }
        asm volatile("cp.async.commit_group;\n");
    };

    auto COMPUTE = [&](int buf) {
        float4 bq[NT];
        #pragma unroll
        for (int nt = 0; nt < NT; nt++)
            bq[nt] = *(const float4*)&Bs[buf][wn*WN + nt*8 + gid][tig4];
        #pragma unroll
        for (int mt = 0; mt < MT; mt++) {
            int m0 = wm*WM + mt*16 + gid;
            float4 a0 = *(const float4*)&As[buf][m0    ][tig4];
            float4 a1 = *(const float4*)&As[buf][m0 + 8][tig4];
            #pragma unroll
            for (int nt = 0; nt < NT; nt++) {
                mma_tf32(acc[mt][nt], FU(a0.x), FU(a1.x), FU(a0.y), FU(a1.y),
                         FU(bq[nt].x), FU(bq[nt].y));
                mma_tf32(acc[mt][nt], FU(a0.z), FU(a1.z), FU(a0.w), FU(a1.w),
                         FU(bq[nt].z), FU(bq[nt].w));
            }
        }
    };

    ISSUE(0, 0);
    ISSUE(1, BK);

    const int niter = K / BK;
    for (int it = 0; it < niter; it++) {
        asm volatile("cp.async.wait_group 1;\n");
        __syncthreads();
        ISSUE((it + NSTAGE - 1) % NSTAGE, (it + NSTAGE - 1) * BK);
        COMPUTE(it % NSTAGE);
    }

    if (lsepart) {
        asm volatile("cp.async.wait_group 0;\n");
        __syncthreads();
        float2* lse_s = (float2*)&As[0][0][0];
        #pragma unroll
        for (int mt = 0; mt < MT; mt++) {
            float va[2][NT*2];
            #pragma unroll
            for (int nt = 0; nt < NT; nt++) {
                int r = row0 + wm*WM + mt*16 + gid;
                int c = col0 + wn*WN + nt*8 + (lane & 3)*2;
                float2 v0 = make_float2(acc[mt][nt][0], acc[mt][nt][1]);
                float2 v1 = make_float2(acc[mt][nt][2], acc[mt][nt][3]);
                if (bias) {
                    float2 bb = *(const float2*)(bias + c);
                    v0.x += bb.x; v0.y += bb.y;
                    v1.x += bb.x; v1.y += bb.y;
                }
                *(float2*)(C + (size_t)r * ldc + c)     = v0;
                *(float2*)(C + (size_t)(r+8) * ldc + c) = v1;
                va[0][nt*2] = v0.x; va[0][nt*2+1] = v0.y;
                va[1][nt*2] = v1.x; va[1][nt*2+1] = v1.y;
            }
            #pragma unroll
            for (int hf = 0; hf < 2; hf++) {
                float mx = va[hf][0];
                #pragma unroll
                for (int j = 1; j < NT*2; j++) mx = fmaxf(mx, va[hf][j]);
                float sm = 0.f;
                #pragma unroll
                for (int j = 0; j < NT*2; j++) sm += __expf(va[hf][j] - mx);
                #pragma unroll
                for (int off = 1; off <= 2; off <<= 1) {
                    float mo = __shfl_xor_sync(0xffffffffu, mx, off);
                    float so = __shfl_xor_sync(0xffffffffu, sm, off);
                    float M = fmaxf(mx, mo);
                    sm = sm*__expf(mx - M) + so*__expf(mo - M);
                    mx = M;
                }
                if ((lane & 3) == 0) {
                    int rl = wm*WM + mt*16 + gid + hf*8;
                    lse_s[rl*WARPS_N + wn] = make_float2(mx, sm);
                }
            }
        }
        __syncthreads();
        if (tid < BM) {
            float2 a = lse_s[tid*WARPS_N];
            #pragma unroll
            for (int w = 1; w < WARPS_N; w++) {
                float2 b = lse_s[tid*WARPS_N + w];
                float M = fmaxf(a.x, b.x);
                a = make_float2(M, a.y*__expf(a.x - M) + b.y*__expf(b.x - M));
            }
            lsepart[(size_t)(row0 + tid) * gridDim.x + blockIdx.x] = a;
        }
        return;
    }

    #pragma unroll
    for (int mt = 0; mt < MT; mt++) {
        #pragma unroll
        for (int nt = 0; nt < NT; nt++) {
            int r = row0 + wm*WM + mt*16 + gid;
            int c = col0 + wn*WN + nt*8 + (lane & 3)*2;
            float2 v0 = make_float2(acc[mt][nt][0], acc[mt][nt][1]);
            float2 v1 = make_float2(acc[mt][nt][2], acc[mt][nt][3]);
            if (bias) {
                float2 bb = *(const float2*)(bias + c);
                v0.x += bb.x; v0.y += bb.y;
                v1.x += bb.x; v1.y += bb.y;
            }
            float* p0 = C + (size_t)r * ldc + c;
            float* p1 = C + (size_t)(r+8) * ldc + c;
            if (accumulate) {
                float2 c0 = *(const float2*)p0;
                float2 c1 = *(const float2*)p1;
                v0.x += c0.x; v0.y += c0.y;
                v1.x += c1.x; v1.y += c1.y;
            }
            if (relu) {
                v0.x = fmaxf(v0.x, 0.f); v0.y = fmaxf(v0.y, 0.f);
                v1.x = fmaxf(v1.x, 0.f); v1.y = fmaxf(v1.y, 0.f);
            }
            if (roundout) {
                v0.x = tf32r(v0.x); v0.y = tf32r(v0.y);
                v1.x = tf32r(v1.x); v1.y = tf32r(v1.y);
            }
            *(float2*)p0 = v0;
            *(float2*)p1 = v1;
        }
    }
}

// ---------------- fused attention (scores + online softmax quirk + AV + suffix corr)
#define AT_SMEM ((128*64 + 64*64 + 64*64 + 128*64 + 256 + 256)*4)

__global__ void __launch_bounds__(256, 2)
attn_kernel(const float* __restrict__ qkv,
            const float* __restrict__ vT,
            const float* __restrict__ sufv,
            float* __restrict__ av)
{
    extern __shared__ float sm[];
    float* Qs   = sm;
    float* Ks   = Qs + 128*64;
    float* Vs   = Ks + 64*64;
    float* Ps   = Vs + 64*64;
    float* rmax = Ps + 128*64;
    float* rsum = rmax + 256;

    const int bh = blockIdx.x;
    const int b = bh / H_, h = bh - b*H_;
    const int row0 = (gridDim.y - 1 - blockIdx.y) * 128;

    const int tid  = threadIdx.x;
    const int lane = tid & 31;
    const int wid  = tid >> 5;
    const int wm   = wid >> 1;
    const int wn   = wid & 1;
    const int gid  = lane >> 2;
    const int tig  = lane & 3;

    {
        const float* qbase = qkv + (size_t)(b*T_ + row0) * QKVW_ + h*HS_;
        #pragma unroll
        for (int i = 0; i < 8; i++) {
            int idx = tid + i*256;
            int r = idx >> 4, c = idx & 15;
            int cc = (c + ((r & 3) << 2)) & 15;
            uint32_t dst = (uint32_t)__cvta_generic_to_shared(Qs + r*64 + cc*4);
            const float* src = qbase + (size_t)r * QKVW_ + c*4;
            asm volatile("cp.async.cg.shared.global [%0], [%1], 16;\n" :: "r"(dst), "l"(src));
        }
        asm volatile("cp.async.commit_group;\n");
    }

    float m_run[2][2], s_run[2][2];
    float acc_o[2][4][4] = {};
    #pragma unroll
    for (int mt = 0; mt < 2; mt++)
        #pragma unroll
        for (int k = 0; k < 2; k++) { m_run[mt][k] = -1e30f; s_run[mt][k] = 0.f; }

    const int jmax = row0/64 + 2;

    for (int j = 0; j < jmax; j++) {
        __syncthreads();
        {
            const float* kbase = qkv + (size_t)(b*T_ + j*64) * QKVW_ + H_*HS_ + h*HS_;
            const float* vbase = vT + (size_t)(h*HS_) * BT_ + b*T_ + j*64;
            #pragma unroll
            for (int i = 0; i < 4; i++) {
                int idx = tid + i*256;
                int r = idx >> 4, c = idx & 15;
                int cc = (c + ((r & 3) << 2)) & 15;
                uint32_t dk = (uint32_t)__cvta_generic_to_shared(Ks + r*64 + cc*4);
                uint32_t dv = (uint32_t)__cvta_generic_to_shared(Vs + r*64 + cc*4);
                const float* sk = kbase + (size_t)r * QKVW_ + c*4;
                const float* sv = vbase + (size_t)r * BT_ + c*4;
                asm volatile("cp.async.cg.shared.global [%0], [%1], 16;\n" :: "r"(dk), "l"(sk));
                asm volatile("cp.async.cg.shared.global [%0], [%1], 16;\n" :: "r"(dv), "l"(sv));
            }
            asm volatile("cp.async.commit_group;\n");
            asm volatile("cp.async.wait_group 0;\n");
        }
        __syncthreads();

        float acc_s[2][4][4] = {};
        #pragma unroll
        for (int ks = 0; ks < 4; ks++) {
            int fidx = ((ks*16 + tig*4) + ((gid & 3) << 4)) & 63;
            float4 bq[4];
            #pragma unroll
            for (int nt = 0; nt < 4; nt++) {
                int n0 = wn*32 + nt*8 + gid;
                bq[nt] = *(const float4*)&Ks[n0*64 + fidx];
            }
            #pragma unroll
            for (int mt = 0; mt < 2; mt++) {
                int m0 = wm*32 + mt*16 + gid;
                float4 a0 = *(const float4*)&Qs[m0*64 + fidx];
                float4 a1 = *(const float4*)&Qs[(m0+8)*64 + fidx];
                #pragma unroll
                for (int nt = 0; nt < 4; nt++) {
                    mma_tf32(acc_s[mt][nt], FU(a0.x), FU(a1.x), FU(a0.y), FU(a1.y),
                             FU(bq[nt].x), FU(bq[nt].y));
                    mma_tf32(acc_s[mt][nt], FU(a0.z), FU(a1.z), FU(a0.w), FU(a1.w),
                             FU(bq[nt].z), FU(bq[nt].w));
                }
            }
        }

        float tmax[2][2];
        #pragma unroll
        for (int mt = 0; mt < 2; mt++) {
            int t0 = row0 + wm*32 + mt*16 + gid;
            int t1 = t0 + 8;
            tmax[mt][0] = -1e30f; tmax[mt][1] = -1e30f;
            #pragma unroll
            for (int nt = 0; nt < 4; nt++) {
                int c0 = j*64 + wn*32 + nt*8 + tig*2;
                float* a = acc_s[mt][nt];
                a[0] = (c0   <= t0) ? a[0]*SCALE_ : -1e30f;
                a[1] = (c0+1 <= t0) ? a[1]*SCALE_ : -1e30f;
                a[2] = (c0   <= t1) ? a[2]*SCALE_ : -1e30f;
                a[3] = (c0+1 <= t1) ? a[3]*SCALE_ : -1e30f;
                tmax[mt][0] = fmaxf(tmax[mt][0], fmaxf(a[0], a[1]));
                tmax[mt][1] = fmaxf(tmax[mt][1], fmaxf(a[2], a[3]));
            }
            #pragma unroll
            for (int off = 1; off <= 2; off <<= 1) {
                tmax[mt][0] = fmaxf(tmax[mt][0], __shfl_xor_sync(0xffffffffu, tmax[mt][0], off));
                tmax[mt][1] = fmaxf(tmax[mt][1], __shfl_xor_sync(0xffffffffu, tmax[mt][1], off));
            }
            if (tig == 0) {
                int rl = wm*32 + mt*16 + gid;
                rmax[rl*2 + wn]     = tmax[mt][0];
                rmax[(rl+8)*2 + wn] = tmax[mt][1];
            }
        }
        __syncthreads();

        float alpha[2][2], psum[2][2];
        #pragma unroll
        for (int mt = 0; mt < 2; mt++) {
            #pragma unroll
            for (int k = 0; k < 2; k++) {
                int rl = wm*32 + mt*16 + gid + k*8;
                float tm = fmaxf(rmax[rl*2], rmax[rl*2+1]);
                float mn = fmaxf(m_run[mt][k], tm);
                alpha[mt][k] = __expf(m_run[mt][k] - mn);
                m_run[mt][k] = mn;
                psum[mt][k] = 0.f;
            }
        }
        #pragma unroll
        for (int mt = 0; mt < 2; mt++) {
            int r0l = wm*32 + mt*16 + gid;
            int rot = (r0l & 3) << 4;
            #pragma unroll
            for (int nt = 0; nt < 4; nt++) {
                float* a = acc_s[mt][nt];
                float p0 = __expf(a[0] - m_run[mt][0]);
                float p1 = __expf(a[1] - m_run[mt][0]);
                float p2 = __expf(a[2] - m_run[mt][1]);
                float p3 = __expf(a[3] - m_run[mt][1]);
                psum[mt][0] += p0 + p1;
                psum[mt][1] += p2 + p3;
                int c = wn*32 + nt*8 + tig*2;
                int f = (c + rot) & 63;
                *(float2*)&Ps[r0l*64 + f]     = make_float2(tf32r(p0), tf32r(p1));
                *(float2*)&Ps[(r0l+8)*64 + f] = make_float2(tf32r(p2), tf32r(p3));
                float* o = acc_o[mt][nt];
                o[0] *= alpha[mt][0]; o[1] *= alpha[mt][0];
                o[2] *= alpha[mt][1]; o[3] *= alpha[mt][1];
            }
            #pragma unroll
            for (int off = 1; off <= 2; off <<= 1) {
                psum[mt][0] += __shfl_xor_sync(0xffffffffu, psum[mt][0], off);
                psum[mt][1] += __shfl_xor_sync(0xffffffffu, psum[mt][1], off);
            }
            if (tig == 0) {
                rsum[r0l*2 + wn]     = psum[mt][0];
                rsum[(r0l+8)*2 + wn] = psum[mt][1];
            }
        }
        __syncthreads();
        #pragma unroll
        for (int mt = 0; mt < 2; mt++) {
            #pragma unroll
            for (int k = 0; k < 2; k++) {
                int rl = wm*32 + mt*16 + gid + k*8;
                float ts = rsum[rl*2] + rsum[rl*2+1];
                s_run[mt][k] = s_run[mt][k]*alpha[mt][k] + ts;
            }
        }

        #pragma unroll
        for (int ks = 0; ks < 4; ks++) {
            int fidx = ((ks*16 + tig*4) + ((gid & 3) << 4)) & 63;
            float4 bq[4];
            #pragma unroll
            for (int nt = 0; nt < 4; nt++) {
                int e0 = wn*32 + nt*8 + gid;
                bq[nt] = *(const float4*)&Vs[e0*64 + fidx];
            }
            #pragma unroll
            for (int mt = 0; mt < 2; mt++) {
                int m0 = wm*32 + mt*16 + gid;
                float4 a0 = *(const float4*)&Ps[m0*64 + fidx];
                float4 a1 = *(const float4*)&Ps[(m0+8)*64 + fidx];
                #pragma unroll
                for (int nt = 0; nt < 4; nt++) {
                    mma_tf32(acc_o[mt][nt], FU(a0.x), FU(a1.x), FU(a0.y), FU(a1.y),
                             FU(bq[nt].x), FU(bq[nt].y));
                    mma_tf32(acc_o[mt][nt], FU(a0.z), FU(a1.z), FU(a0.w), FU(a1.w),
                             FU(bq[nt].z), FU(bq[nt].w));
                }
            }
        }
    }

    // final: analytic masked mass, normalize, fused suffix-V correction, tf32 round
    float oscale[2][2], wmr[2][2];
    #pragma unroll
    for (int mt = 0; mt < 2; mt++) {
        #pragma unroll
        for (int k = 0; k < 2; k++) {
            int t = row0 + wm*32 + mt*16 + gid + k*8;
            float mr = m_run[mt][k], sr = s_run[mt][k];
            int count = T_ - 1 - t;
            float mf = (count > 0) ? fmaxf(mr, 0.f) : mr;
            float emm = __expf(mr - mf);
            float denom = sr * emm + (float)count * __expf(-mf);
            oscale[mt][k] = emm / denom;
            wmr[mt][k]    = __expf(-mf) / denom;
        }
    }
    #pragma unroll
    for (int mt = 0; mt < 2; mt++) {
        int r = row0 + wm*32 + mt*16 + gid;
        const float* suf0 = sufv + ((size_t)bh*T_ + r) * HS_;
        const float* suf1 = suf0 + (size_t)8 * HS_;
        #pragma unroll
        for (int nt = 0; nt < 4; nt++) {
            int c = wn*32 + nt*8 + tig*2;
            float* dst = av + (size_t)(b*T_ + r)*D_ + h*HS_ + c;
            float* o = acc_o[mt][nt];
            float2 sv0 = *(const float2*)(suf0 + c);
            float2 sv1 = *(const float2*)(suf1 + c);
            *(float2*)dst = make_float2(
                tf32r(fmaf(wmr[mt][0], sv0.x, o[0]*oscale[mt][0])),
                tf32r(fmaf(wmr[mt][0], sv0.y, o[1]*oscale[mt][0])));
            *(float2*)(dst + 8*D_) = make_float2(
                tf32r(fmaf(wmr[mt][1], sv1.x, o[2]*oscale[mt][1])),
                tf32r(fmaf(wmr[mt][1], sv1.y, o[3]*oscale[mt][1])));
        }
    }
}

// ---------------- parallel V suffix scan ----------------
__global__ void suffixv_kernel(const float* __restrict__ vT, float* __restrict__ suf)
{
    int gw   = blockIdx.x * 8 + (threadIdx.x >> 5);
    int lane = threadIdx.x & 31;
    int e  = gw >> 2;
    int b  = gw & 3;
    int bh = b * H_ + (e >> 6);
    int ep = e & 63;
    const float* src = vT + (size_t)e * BT_ + b * T_;
    float* dst = suf + (size_t)bh * T_ * HS_ + ep;

    float carry = 0.f;
    for (int j = 31; j >= 0; j--) {
        int t = j*32 + lane;
        float v = src[t];
        float s = v;
        #pragma unroll
        for (int off = 1; off < 32; off <<= 1) {
            float o = __shfl_down_sync(0xffffffffu, s, off);
            if (lane + off < 32) s += o;
        }
        dst[(size_t)t * HS_] = s - v + carry;
        carry += __shfl_sync(0xffffffffu, s, 0);
    }
}

// ---------------- loss from LM-head partials ----------------
__global__ void lossrow2_kernel(const float2* __restrict__ part, int nch,
                                const float* __restrict__ logits,
                                const int* __restrict__ tgt,
                                float* __restrict__ rowloss)
{
    int row  = blockIdx.x;
    int lane = threadIdx.x;
    float m = -1e30f, s = 0.f;
    for (int i = lane; i < nch; i += 32) {
        float2 p = part[(size_t)row*nch + i];
        float M = fmaxf(m, p.x);
        s = s*__expf(m - M) + p.y*__expf(p.x - M);
        m = M;
    }
    #pragma unroll
    for (int off = 16; off > 0; off >>= 1) {
        float mo = __shfl_xor_sync(0xffffffffu, m, off);
        float so = __shfl_xor_sync(0xffffffffu, s, off);
        float M = fmaxf(m, mo);
        s = s*__expf(m - M) + so*__expf(mo - M);
        m = M;
    }
    if (lane == 0)
        rowloss[row] = m + logf(s) - logits[(size_t)row*V_ + tgt[row]];
}

__global__ void lossreduce_kernel(const float* __restrict__ rowloss,
                                  float* __restrict__ out)
{
    __shared__ float red[256];
    int tid = threadIdx.x;
    float s = 0.f;
    for (int i = tid; i < BT_; i += 256) s += rowloss[i];
    red[tid] = s; __syncthreads();
    for (int off = 128; off > 0; off >>= 1) {
        if (tid < off) red[tid] += red[tid+off];
        __syncthreads();
    }
    if (tid == 0) out[0] = red[0] / (float)BT_;
}

// ---------------- host ----------------
static float* sym(const void* s)
{
    void* p = nullptr;
    cudaGetSymbolAddress(&p, s);
    return (float*)p;
}

struct GemmArgs {
    const float *A, *B; float* C; const float* bias;
    int M, N, K, lda, ldb, ldc;
    bool acc, relu, round;
    float2* lsepart;
    int Z, zdiv;
    long long sAd, sAm, sBd, sBm, sCd, sCm;
};

static void gemm128x128(const GemmArgs& g)
{
    dim3 grid(g.N / 128, g.M / 128, g.Z);
    ntgemm_kernel<128,128,64,32><<<grid, 256>>>(
        g.A, g.B, g.C, g.bias, g.K, g.lda, g.ldb, g.ldc,
        g.acc, g.relu, g.round, g.lsepart, g.zdiv,
        g.sAd, g.sAm, g.sBd, g.sBm, g.sCd, g.sCm);
}

static void transpose(const float* in, float* out, int R, int C,
                      int ldi, int ldo, int Z, int zdiv, int roundout,
                      long long sId, long long sIm,
                      long long sOd, long long sOm)
{
    dim3 grid(C / 32, R / 32, Z);
    transpose_kernel<<<grid, dim3(32, 8)>>>(in, out, ldi, ldo, zdiv, roundout,
                                            sId, sIm, sOd, sOm);
}

extern "C" void kernel_launch(void* const* d_in, const int* in_sizes, int n_in,
                              void* d_out, int out_size)
{
    const int*   token_ids = (const int*)d_in[0];
    const int*   targets   = (const int*)d_in[1];
    const float* tok_table = (const float*)d_in[2];
    const float* pos_table = (const float*)d_in[3];
    const float* ln1_g = (const float*)d_in[4];
    const float* ln1_b = (const float*)d_in[5];
    const float* Wq = (const float*)d_in[6];
    const float* Wk = (const float*)d_in[7];
    const float* Wv = (const float*)d_in[8];
    const float* Wo = (const float*)d_in[9];
    const float* ln2_g = (const float*)d_in[10];
    const float* ln2_b = (const float*)d_in[11];
    const float* W1 = (const float*)d_in[12];
    const float* b1 = (const float*)d_in[13];
    const float* W2 = (const float*)d_in[14];
    const float* b2 = (const float*)d_in[15];
    const float* lnf_g = (const float*)d_in[16];
    const float* lnf_b = (const float*)d_in[17];
    const float* Wlm = (const float*)d_in[18];
    const float* blm = (const float*)d_in[19];

    cudaFuncSetAttribute(attn_kernel,
                         cudaFuncAttributeMaxDynamicSharedMemorySize, AT_SMEM);

    float* x    = sym(g_x);
    float* h    = sym(g_h);
    float* qkv  = sym(g_qkv);
    float* wp   = sym(g_wpack);
    float* woT  = sym(g_woT);
    float* w1T  = sym(g_w1T);
    float* w2T  = sym(g_w2T);
    float* wlmT = sym(g_wlmT);
    float* vT   = sym(g_vT);
    float* av   = sym(g_av);
    float* ffn  = sym(g_ffn);
    float* sufv = sym(g_sufv);
    float2* lsp = (float2*)sym(g_lsepart);
    float* rl   = sym(g_rowloss);

    const long long NLOGITS = (long long)BT_ * V_;
    float* out = (float*)d_out;
    bool out_has_logits = ((long long)out_size >= NLOGITS);
    float* logits = out_has_logits ? out : sym(g_logits);

    // ---- embed ----
    embed_kernel<<<(BT_*D_ + 255)/256, 256>>>(token_ids, tok_table, pos_table, x);

    // ---- weight packs ----
    for (int grp = 0; grp < 3; grp++) {
        const float* W = (grp == 0) ? Wq : (grp == 1) ? Wk : Wv;
        transpose(W, wp + (long long)grp*H_*HS_*D_, D_, HS_, HS_, D_,
                  L_*H_, H_, 1,
                  (long long)H_*D_*HS_, (long long)D_*HS_,
                  (long long)QKVW_*D_, (long long)HS_*D_);
    }
    transpose(Wo, woT, H_*HS_, D_, D_, H_*HS_, L_, 1, 1,
              (long long)H_*HS_*D_, 0, (long long)D_*H_*HS_, 0);
    transpose(W1, w1T, D_, DFF_, DFF_, D_, L_, 1, 1,
              (long long)D_*DFF_, 0, (long long)DFF_*D_, 0);
    transpose(W2, w2T, DFF_, D_, D_, DFF_, L_, 1, 1,
              (long long)DFF_*D_, 0, (long long)D_*DFF_, 0);
    transpose(Wlm, wlmT, D_, V_, V_, D_, 1, 1, 1, 0, 0, 0, 0);

    for (int l = 0; l < L_; l++) {
        ln_kernel<<<BT_, 128>>>(x, ln1_g + l*D_, ln1_b + l*D_, h);

        // fused QKV (rounded)
        {
            GemmArgs g{h, wp + (long long)l*QKVW_*D_, qkv, nullptr,
                       BT_, QKVW_, D_, D_, D_, QKVW_,
                       false, false, true, nullptr, 1, 1, 0,0,0,0,0,0};
            gemm128x128(g);
        }

        // V^T, suffix scan
        transpose(qkv + 2*H_*HS_, vT, BT_, D_, QKVW_, BT_, 1, 1, 0, 0, 0, 0, 0);
        suffixv_kernel<<<192, 256>>>(vT, sufv);

        // fused attention (+ suffix-V correction in epilogue)
        attn_kernel<<<dim3(B_*H_, T_/128), 256, AT_SMEM>>>(qkv, vT, sufv, av);

        // x += av @ Wo[l]
        {
            GemmArgs g{av, woT + (long long)l*D_*H_*HS_, x, nullptr,
                       BT_, D_, H_*HS_, H_*HS_, H_*HS_, D_,
                       true, false, false, nullptr, 1, 1, 0,0,0,0,0,0};
            gemm128x128(g);
        }

        ln_kernel<<<BT_, 128>>>(x, ln2_g + l*D_, ln2_b + l*D_, h);

        // ffn
        {
            GemmArgs g{h, w1T + (long long)l*DFF_*D_, ffn, b1 + l*DFF_,
                       BT_, DFF_, D_, D_, D_, DFF_,
                       false, true, true, nullptr, 1, 1, 0,0,0,0,0,0};
            gemm128x128(g);
        }
        {
            GemmArgs g{ffn, w2T + (long long)l*D_*DFF_, x, b2 + l*D_,
                       BT_, D_, DFF_, DFF_, DFF_, D_,
                       true, false, false, nullptr, 1, 1, 0,0,0,0,0,0};
            gemm128x128(g);
        }
    }

    ln_kernel<<<BT_, 128>>>(x, lnf_g, lnf_b, h);

    // LM head with fused LSE partials (250 chunks)
    {
        GemmArgs g{h, wlmT, logits, blm,
                   BT_, V_, D_, D_, D_, V_,
                   false, false, false, lsp, 1, 1, 0,0,0,0,0,0};
        gemm128x128(g);
    }

    lossrow2_kernel<<<BT_, 32>>>(lsp, NCH_, logits, targets, rl);
    if (out_has_logits && (long long)out_size > NLOGITS) {
        lossreduce_kernel<<<1, 256>>>(rl, out + NLOGITS);
    } else if (!out_has_logits && out_size >= 1) {
        lossreduce_kernel<<<1, 256>>>(rl, out);
    }
}

// round 15
// speedup vs baseline: 1.5402x; 1.0080x over previous
#include <cuda_runtime.h>
#include <cuda_bf16.h>
#include <math.h>
#include <stdint.h>

// Problem dims
#define B_  4
#define T_  1024
#define V_  32000
#define D_  384
#define H_  6
#define HS_ 64
#define L_  6
#define DFF_ 1536
#define BT_ (B_*T_)
#define QKVW_ (3*H_*HS_)   // 1152
#define NCH_ (V_/128)      // lsepart capacity
#define EPS_ 1e-5f
#define SCALE_ 0.125f

// ---------------- static scratch ----------------
__device__ float g_x[BT_*D_];
__device__ float g_h[BT_*D_];
__device__ float g_qkv[(size_t)BT_*QKVW_];
__device__ float g_wpack[(size_t)L_*QKVW_*D_];
__device__ float g_woT[(size_t)L_*D_*(H_*HS_)];
__device__ float g_w1T[(size_t)L_*DFF_*D_];
__device__ float g_w2T[(size_t)L_*D_*DFF_];
__device__ float g_wlmT[(size_t)V_*D_];
__device__ float g_vT[(size_t)D_*BT_];
__device__ float g_av[BT_*D_];
__device__ float g_ffn[BT_*DFF_];
__device__ float g_sufv[(size_t)B_*H_*T_*HS_];
__device__ float2 g_lsepart[(size_t)BT_*NCH_];
__device__ float g_rowloss[BT_];
__device__ float g_logits[(size_t)BT_*V_];

// ---------------- tf32 helper ----------------
__device__ __forceinline__ float tf32r(float x)
{
    asm("cvt.rna.tf32.f32 %0, %0;" : "+f"(x));
    return x;
}
#define FU(x) __float_as_uint(x)

// ---------------- embed ----------------
__global__ void embed_kernel(const int* __restrict__ tok,
                             const float* __restrict__ tt,
                             const float* __restrict__ pt,
                             float* __restrict__ x)
{
    int idx = blockIdx.x * blockDim.x + threadIdx.x;
    if (idx >= BT_*D_) return;
    int bt = idx / D_;
    int d  = idx - bt * D_;
    int t  = bt % T_;
    x[idx] = tt[(size_t)tok[bt] * D_ + d] + pt[t * D_ + d];
}

// ---------------- tiled transpose ----------------
__global__ void transpose_kernel(const float* __restrict__ in,
                                 float* __restrict__ out,
                                 int ldi, int ldo, int zdiv, int roundout,
                                 long long sId, long long sIm,
                                 long long sOd, long long sOm)
{
    __shared__ float tile[32][33];
    int z  = blockIdx.z;
    int zq = z / zdiv;
    int zr = z - zq * zdiv;
    in  += zq * sId + (long long)zr * sIm;
    out += zq * sOd + (long long)zr * sOm;

    int r0 = blockIdx.y * 32;
    int c0 = blockIdx.x * 32;
    int tx = threadIdx.x, ty = threadIdx.y;
    #pragma unroll
    for (int j = 0; j < 4; j++)
        tile[ty + 8*j][tx] = in[(size_t)(r0 + ty + 8*j) * ldi + c0 + tx];
    __syncthreads();
    #pragma unroll
    for (int j = 0; j < 4; j++) {
        float v = tile[tx][ty + 8*j];
        if (roundout) v = tf32r(v);
        out[(size_t)(c0 + ty + 8*j) * ldo + r0 + tx] = v;
    }
}

// ---------------- layernorm: warp per row, float4, shfl reductions ----------------
// grid = BT_/8 blocks of 256 (8 warps). D = 384 = 32 lanes * 3 float4.
__global__ void ln_kernel(const float* __restrict__ x,
                          const float* __restrict__ g,
                          const float* __restrict__ b,
                          float* __restrict__ y)
{
    int warp = threadIdx.x >> 5;
    int lane = threadIdx.x & 31;
    size_t row = (size_t)blockIdx.x * 8 + warp;
    const float4* xr = (const float4*)(x + row * D_);
    const float4* g4 = (const float4*)g;
    const float4* b4 = (const float4*)b;
    float4* yr = (float4*)(y + row * D_);

    float4 v[3];
    float s = 0.f, q = 0.f;
    #pragma unroll
    for (int i = 0; i < 3; i++) {
        v[i] = xr[lane + i*32];
        s += v[i].x + v[i].y + v[i].z + v[i].w;
        q += v[i].x*v[i].x + v[i].y*v[i].y + v[i].z*v[i].z + v[i].w*v[i].w;
    }
    #pragma unroll
    for (int off = 16; off > 0; off >>= 1) {
        s += __shfl_xor_sync(0xffffffffu, s, off);
        q += __shfl_xor_sync(0xffffffffu, q, off);
    }
    float mean = s * (1.0f / D_);
    float var  = q * (1.0f / D_) - mean * mean;
    float inv  = rsqrtf(var + EPS_);
    #pragma unroll
    for (int i = 0; i < 3; i++) {
        float4 gg = g4[lane + i*32];
        float4 bb = b4[lane + i*32];
        float4 o;
        o.x = tf32r((v[i].x - mean) * inv * gg.x + bb.x);
        o.y = tf32r((v[i].y - mean) * inv * gg.y + bb.y);
        o.z = tf32r((v[i].z - mean) * inv * gg.z + bb.z);
        o.w = tf32r((v[i].w - mean) * inv * gg.w + bb.w);
        yr[lane + i*32] = o;
    }
}

__device__ __forceinline__ void mma_tf32(float c[4],
    uint32_t a0, uint32_t a1, uint32_t a2, uint32_t a3,
    uint32_t b0, uint32_t b1)
{
    asm volatile(
        "mma.sync.aligned.m16n8k8.row.col.f32.tf32.tf32.f32 "
        "{%0,%1,%2,%3}, {%4,%5,%6,%7}, {%8,%9}, {%0,%1,%2,%3};"
        : "+f"(c[0]), "+f"(c[1]), "+f"(c[2]), "+f"(c[3])
        : "r"(a0), "r"(a1), "r"(a2), "r"(a3), "r"(b0), "r"(b1));
}

// ---------------- NT tensor-core GEMM, cp.async 3-stage (static smem, occ 2) ----
template<int BM, int BN, int WM, int WN>
__global__ void __launch_bounds__(256, 2)
ntgemm_kernel(const float* __restrict__ A,
              const float* __restrict__ B,
              float* __restrict__ C,
              const float* __restrict__ bias,
              int K, int lda, int ldb, int ldc,
              int accumulate, int relu, int roundout,
              float2* lsepart, int zdiv,
              long long sAd, long long sAm,
              long long sBd, long long sBm,
              long long sCd, long long sCm)
{
    constexpr int BK = 16;
    constexpr int NSTAGE = 3;
    constexpr int MT = WM / 16;
    constexpr int NT = WN / 8;
    constexpr int WARPS_N = BN / WN;
    static_assert((BM/WM) * (BN/WN) == 8, "8 warps");
    constexpr int APT = BM / 64;
    constexpr int BPT = BN / 64;

    __shared__ float As[NSTAGE][BM][BK];
    __shared__ float Bs[NSTAGE][BN][BK];

    const int row0 = blockIdx.y * BM;
    const int col0 = blockIdx.x * BN;

    int z  = blockIdx.z;
    int zq = z / zdiv;
    int zr = z - zq * zdiv;
    A += zq * sAd + (long long)zr * sAm;
    B += zq * sBd + (long long)zr * sBm;
    C += zq * sCd + (long long)zr * sCm;

    const int tid  = threadIdx.x;
    const int lane = tid & 31;
    const int wid  = tid >> 5;
    const int wm   = wid / WARPS_N;
    const int wn   = wid % WARPS_N;
    const int gid  = lane >> 2;
    const int tig4 = (lane & 3) * 4;

    float acc[MT][NT][4] = {};

    const int s_row = tid >> 2;
    const int s_kq  = (tid & 3) * 4;

    auto ISSUE = [&](int stage, int k0) {
        if (k0 < K) {
            #pragma unroll
            for (int i = 0; i < APT; i++) {
                uint32_t dst = (uint32_t)__cvta_generic_to_shared(&As[stage][s_row + i*64][s_kq]);
                const float* src = A + (size_t)(row0 + s_row + i*64) * lda + k0 + s_kq;
                asm volatile("cp.async.cg.shared.global [%0], [%1], 16;\n" :: "r"(dst), "l"(src));
            }
            #pragma unroll
            for (int i = 0; i < BPT; i++) {
                uint32_t dst = (uint32_t)__cvta_generic_to_shared(&Bs[stage][s_row + i*64][s_kq]);
                const float* src = B + (size_t)(col0 + s_row + i*64) * ldb + k0 + s_kq;
                asm volatile("cp.async.cg.shared.global [%0], [%1], 16;\n" :: "r"(dst), "l"(src));
            }
        }
        asm volatile("cp.async.commit_group;\n");
    };

    auto COMPUTE = [&](int buf) {
        float4 bq[NT];
        #pragma unroll
        for (int nt = 0; nt < NT; nt++)
            bq[nt] = *(const float4*)&Bs[buf][wn*WN + nt*8 + gid][tig4];
        #pragma unroll
        for (int mt = 0; mt < MT; mt++) {
            int m0 = wm*WM + mt*16 + gid;
            float4 a0 = *(const float4*)&As[buf][m0    ][tig4];
            float4 a1 = *(const float4*)&As[buf][m0 + 8][tig4];
            #pragma unroll
            for (int nt = 0; nt < NT; nt++) {
                mma_tf32(acc[mt][nt], FU(a0.x), FU(a1.x), FU(a0.y), FU(a1.y),
                         FU(bq[nt].x), FU(bq[nt].y));
                mma_tf32(acc[mt][nt], FU(a0.z), FU(a1.z), FU(a0.w), FU(a1.w),
                         FU(bq[nt].z), FU(bq[nt].w));
            }
        }
    };

    ISSUE(0, 0);
    ISSUE(1, BK);

    const int niter = K / BK;
    for (int it = 0; it < niter; it++) {
        asm volatile("cp.async.wait_group 1;\n");
        __syncthreads();
        ISSUE((it + NSTAGE - 1) % NSTAGE, (it + NSTAGE - 1) * BK);
        COMPUTE(it % NSTAGE);
    }

    if (lsepart) {
        asm volatile("cp.async.wait_group 0;\n");
        __syncthreads();
        float2* lse_s = (float2*)&As[0][0][0];
        #pragma unroll
        for (int mt = 0; mt < MT; mt++) {
            float va[2][NT*2];
            #pragma unroll
            for (int nt = 0; nt < NT; nt++) {
                int r = row0 + wm*WM + mt*16 + gid;
                int c = col0 + wn*WN + nt*8 + (lane & 3)*2;
                float2 v0 = make_float2(acc[mt][nt][0], acc[mt][nt][1]);
                float2 v1 = make_float2(acc[mt][nt][2], acc[mt][nt][3]);
                if (bias) {
                    float2 bb = *(const float2*)(bias + c);
                    v0.x += bb.x; v0.y += bb.y;
                    v1.x += bb.x; v1.y += bb.y;
                }
                *(float2*)(C + (size_t)r * ldc + c)     = v0;
                *(float2*)(C + (size_t)(r+8) * ldc + c) = v1;
                va[0][nt*2] = v0.x; va[0][nt*2+1] = v0.y;
                va[1][nt*2] = v1.x; va[1][nt*2+1] = v1.y;
            }
            #pragma unroll
            for (int hf = 0; hf < 2; hf++) {
                float mx = va[hf][0];
                #pragma unroll
                for (int j = 1; j < NT*2; j++) mx = fmaxf(mx, va[hf][j]);
                float sm = 0.f;
                #pragma unroll
                for (int j = 0; j < NT*2; j++) sm += __expf(va[hf][j] - mx);
                #pragma unroll
                for (int off = 1; off <= 2; off <<= 1) {
                    float mo = __shfl_xor_sync(0xffffffffu, mx, off);
                    float so = __shfl_xor_sync(0xffffffffu, sm, off);
                    float M = fmaxf(mx, mo);
                    sm = sm*__expf(mx - M) + so*__expf(mo - M);
                    mx = M;
                }
                if ((lane & 3) == 0) {
                    int rl = wm*WM + mt*16 + gid + hf*8;
                    lse_s[rl*WARPS_N + wn] = make_float2(mx, sm);
                }
            }
        }
        __syncthreads();
        if (tid < BM) {
            float2 a = lse_s[tid*WARPS_N];
            #pragma unroll
            for (int w = 1; w < WARPS_N; w++) {
                float2 b = lse_s[tid*WARPS_N + w];
                float M = fmaxf(a.x, b.x);
                a = make_float2(M, a.y*__expf(a.x - M) + b.y*__expf(b.x - M));
            }
            lsepart[(size_t)(row0 + tid) * gridDim.x + blockIdx.x] = a;
        }
        return;
    }

    #pragma unroll
    for (int mt = 0; mt < MT; mt++) {
        #pragma unroll
        for (int nt = 0; nt < NT; nt++) {
            int r = row0 + wm*WM + mt*16 + gid;
            int c = col0 + wn*WN + nt*8 + (lane & 3)*2;
            float2 v0 = make_float2(acc[mt][nt][0], acc[mt][nt][1]);
            float2 v1 = make_float2(acc[mt][nt][2], acc[mt][nt][3]);
            if (bias) {
                float2 bb = *(const float2*)(bias + c);
                v0.x += bb.x; v0.y += bb.y;
                v1.x += bb.x; v1.y += bb.y;
            }
            float* p0 = C + (size_t)r * ldc + c;
            float* p1 = C + (size_t)(r+8) * ldc + c;
            if (accumulate) {
                float2 c0 = *(const float2*)p0;
                float2 c1 = *(const float2*)p1;
                v0.x += c0.x; v0.y += c0.y;
                v1.x += c1.x; v1.y += c1.y;
            }
            if (relu) {
                v0.x = fmaxf(v0.x, 0.f); v0.y = fmaxf(v0.y, 0.f);
                v1.x = fmaxf(v1.x, 0.f); v1.y = fmaxf(v1.y, 0.f);
            }
            if (roundout) {
                v0.x = tf32r(v0.x); v0.y = tf32r(v0.y);
                v1.x = tf32r(v1.x); v1.y = tf32r(v1.y);
            }
            *(float2*)p0 = v0;
            *(float2*)p1 = v1;
        }
    }
}

// ---------------- fused attention (scores + online softmax quirk + AV + suffix corr)
#define AT_SMEM ((128*64 + 64*64 + 64*64 + 128*64 + 256 + 256)*4)

__global__ void __launch_bounds__(256, 2)
attn_kernel(const float* __restrict__ qkv,
            const float* __restrict__ vT,
            const float* __restrict__ sufv,
            float* __restrict__ av)
{
    extern __shared__ float sm[];
    float* Qs   = sm;
    float* Ks   = Qs + 128*64;
    float* Vs   = Ks + 64*64;
    float* Ps   = Vs + 64*64;
    float* rmax = Ps + 128*64;
    float* rsum = rmax + 256;

    const int bh = blockIdx.x;
    const int b = bh / H_, h = bh - b*H_;
    const int row0 = (gridDim.y - 1 - blockIdx.y) * 128;

    const int tid  = threadIdx.x;
    const int lane = tid & 31;
    const int wid  = tid >> 5;
    const int wm   = wid >> 1;
    const int wn   = wid & 1;
    const int gid  = lane >> 2;
    const int tig  = lane & 3;

    {
        const float* qbase = qkv + (size_t)(b*T_ + row0) * QKVW_ + h*HS_;
        #pragma unroll
        for (int i = 0; i < 8; i++) {
            int idx = tid + i*256;
            int r = idx >> 4, c = idx & 15;
            int cc = (c + ((r & 3) << 2)) & 15;
            uint32_t dst = (uint32_t)__cvta_generic_to_shared(Qs + r*64 + cc*4);
            const float* src = qbase + (size_t)r * QKVW_ + c*4;
            asm volatile("cp.async.cg.shared.global [%0], [%1], 16;\n" :: "r"(dst), "l"(src));
        }
        asm volatile("cp.async.commit_group;\n");
    }

    float m_run[2][2], s_run[2][2];
    float acc_o[2][4][4] = {};
    #pragma unroll
    for (int mt = 0; mt < 2; mt++)
        #pragma unroll
        for (int k = 0; k < 2; k++) { m_run[mt][k] = -1e30f; s_run[mt][k] = 0.f; }

    const int jmax = row0/64 + 2;

    for (int j = 0; j < jmax; j++) {
        __syncthreads();
        {
            const float* kbase = qkv + (size_t)(b*T_ + j*64) * QKVW_ + H_*HS_ + h*HS_;
            const float* vbase = vT + (size_t)(h*HS_) * BT_ + b*T_ + j*64;
            #pragma unroll
            for (int i = 0; i < 4; i++) {
                int idx = tid + i*256;
                int r = idx >> 4, c = idx & 15;
                int cc = (c + ((r & 3) << 2)) & 15;
                uint32_t dk = (uint32_t)__cvta_generic_to_shared(Ks + r*64 + cc*4);
                uint32_t dv = (uint32_t)__cvta_generic_to_shared(Vs + r*64 + cc*4);
                const float* sk = kbase + (size_t)r * QKVW_ + c*4;
                const float* sv = vbase + (size_t)r * BT_ + c*4;
                asm volatile("cp.async.cg.shared.global [%0], [%1], 16;\n" :: "r"(dk), "l"(sk));
                asm volatile("cp.async.cg.shared.global [%0], [%1], 16;\n" :: "r"(dv), "l"(sv));
            }
            asm volatile("cp.async.commit_group;\n");
            asm volatile("cp.async.wait_group 0;\n");
        }
        __syncthreads();

        float acc_s[2][4][4] = {};
        #pragma unroll
        for (int ks = 0; ks < 4; ks++) {
            int fidx = ((ks*16 + tig*4) + ((gid & 3) << 4)) & 63;
            float4 bq[4];
            #pragma unroll
            for (int nt = 0; nt < 4; nt++) {
                int n0 = wn*32 + nt*8 + gid;
                bq[nt] = *(const float4*)&Ks[n0*64 + fidx];
            }
            #pragma unroll
            for (int mt = 0; mt < 2; mt++) {
                int m0 = wm*32 + mt*16 + gid;
                float4 a0 = *(const float4*)&Qs[m0*64 + fidx];
                float4 a1 = *(const float4*)&Qs[(m0+8)*64 + fidx];
                #pragma unroll
                for (int nt = 0; nt < 4; nt++) {
                    mma_tf32(acc_s[mt][nt], FU(a0.x), FU(a1.x), FU(a0.y), FU(a1.y),
                             FU(bq[nt].x), FU(bq[nt].y));
                    mma_tf32(acc_s[mt][nt], FU(a0.z), FU(a1.z), FU(a0.w), FU(a1.w),
                             FU(bq[nt].z), FU(bq[nt].w));
                }
            }
        }

        float tmax[2][2];
        #pragma unroll
        for (int mt = 0; mt < 2; mt++) {
            int t0 = row0 + wm*32 + mt*16 + gid;
            int t1 = t0 + 8;
            tmax[mt][0] = -1e30f; tmax[mt][1] = -1e30f;
            #pragma unroll
            for (int nt = 0; nt < 4; nt++) {
                int c0 = j*64 + wn*32 + nt*8 + tig*2;
                float* a = acc_s[mt][nt];
                a[0] = (c0   <= t0) ? a[0]*SCALE_ : -1e30f;
                a[1] = (c0+1 <= t0) ? a[1]*SCALE_ : -1e30f;
                a[2] = (c0   <= t1) ? a[2]*SCALE_ : -1e30f;
                a[3] = (c0+1 <= t1) ? a[3]*SCALE_ : -1e30f;
                tmax[mt][0] = fmaxf(tmax[mt][0], fmaxf(a[0], a[1]));
                tmax[mt][1] = fmaxf(tmax[mt][1], fmaxf(a[2], a[3]));
            }
            #pragma unroll
            for (int off = 1; off <= 2; off <<= 1) {
                tmax[mt][0] = fmaxf(tmax[mt][0], __shfl_xor_sync(0xffffffffu, tmax[mt][0], off));
                tmax[mt][1] = fmaxf(tmax[mt][1], __shfl_xor_sync(0xffffffffu, tmax[mt][1], off));
            }
            if (tig == 0) {
                int rl = wm*32 + mt*16 + gid;
                rmax[rl*2 + wn]     = tmax[mt][0];
                rmax[(rl+8)*2 + wn] = tmax[mt][1];
            }
        }
        __syncthreads();

        float alpha[2][2], psum[2][2];
        #pragma unroll
        for (int mt = 0; mt < 2; mt++) {
            #pragma unroll
            for (int k = 0; k < 2; k++) {
                int rl = wm*32 + mt*16 + gid + k*8;
                float tm = fmaxf(rmax[rl*2], rmax[rl*2+1]);
                float mn = fmaxf(m_run[mt][k], tm);
                alpha[mt][k] = __expf(m_run[mt][k] - mn);
                m_run[mt][k] = mn;
                psum[mt][k] = 0.f;
            }
        }
        #pragma unroll
        for (int mt = 0; mt < 2; mt++) {
            int r0l = wm*32 + mt*16 + gid;
            int rot = (r0l & 3) << 4;
            #pragma unroll
            for (int nt = 0; nt < 4; nt++) {
                float* a = acc_s[mt][nt];
                float p0 = __expf(a[0] - m_run[mt][0]);
                float p1 = __expf(a[1] - m_run[mt][0]);
                float p2 = __expf(a[2] - m_run[mt][1]);
                float p3 = __expf(a[3] - m_run[mt][1]);
                psum[mt][0] += p0 + p1;
                psum[mt][1] += p2 + p3;
                int c = wn*32 + nt*8 + tig*2;
                int f = (c + rot) & 63;
                *(float2*)&Ps[r0l*64 + f]     = make_float2(tf32r(p0), tf32r(p1));
                *(float2*)&Ps[(r0l+8)*64 + f] = make_float2(tf32r(p2), tf32r(p3));
                float* o = acc_o[mt][nt];
                o[0] *= alpha[mt][0]; o[1] *= alpha[mt][0];
                o[2] *= alpha[mt][1]; o[3] *= alpha[mt][1];
            }
            #pragma unroll
            for (int off = 1; off <= 2; off <<= 1) {
                psum[mt][0] += __shfl_xor_sync(0xffffffffu, psum[mt][0], off);
                psum[mt][1] += __shfl_xor_sync(0xffffffffu, psum[mt][1], off);
            }
            if (tig == 0) {
                rsum[r0l*2 + wn]     = psum[mt][0];
                rsum[(r0l+8)*2 + wn] = psum[mt][1];
            }
        }
        __syncthreads();
        #pragma unroll
        for (int mt = 0; mt < 2; mt++) {
            #pragma unroll
            for (int k = 0; k < 2; k++) {
                int rl = wm*32 + mt*16 + gid + k*8;
                float ts = rsum[rl*2] + rsum[rl*2+1];
                s_run[mt][k] = s_run[mt][k]*alpha[mt][k] + ts;
            }
        }

        #pragma unroll
        for (int ks = 0; ks < 4; ks++) {
            int fidx = ((ks*16 + tig*4) + ((gid & 3) << 4)) & 63;
            float4 bq[4];
            #pragma unroll
            for (int nt = 0; nt < 4; nt++) {
                int e0 = wn*32 + nt*8 + gid;
                bq[nt] = *(const float4*)&Vs[e0*64 + fidx];
            }
            #pragma unroll
            for (int mt = 0; mt < 2; mt++) {
                int m0 = wm*32 + mt*16 + gid;
                float4 a0 = *(const float4*)&Ps[m0*64 + fidx];
                float4 a1 = *(const float4*)&Ps[(m0+8)*64 + fidx];
                #pragma unroll
                for (int nt = 0; nt < 4; nt++) {
                    mma_tf32(acc_o[mt][nt], FU(a0.x), FU(a1.x), FU(a0.y), FU(a1.y),
                             FU(bq[nt].x), FU(bq[nt].y));
                    mma_tf32(acc_o[mt][nt], FU(a0.z), FU(a1.z), FU(a0.w), FU(a1.w),
                             FU(bq[nt].z), FU(bq[nt].w));
                }
            }
        }
    }

    float oscale[2][2], wmr[2][2];
    #pragma unroll
    for (int mt = 0; mt < 2; mt++) {
        #pragma unroll
        for (int k = 0; k < 2; k++) {
            int t = row0 + wm*32 + mt*16 + gid + k*8;
            float mr = m_run[mt][k], sr = s_run[mt][k];
            int count = T_ - 1 - t;
            float mf = (count > 0) ? fmaxf(mr, 0.f) : mr;
            float emm = __expf(mr - mf);
            float denom = sr * emm + (float)count * __expf(-mf);
            oscale[mt][k] = emm / denom;
            wmr[mt][k]    = __expf(-mf) / denom;
        }
    }
    #pragma unroll
    for (int mt = 0; mt < 2; mt++) {
        int r = row0 + wm*32 + mt*16 + gid;
        const float* suf0 = sufv + ((size_t)bh*T_ + r) * HS_;
        const float* suf1 = suf0 + (size_t)8 * HS_;
        #pragma unroll
        for (int nt = 0; nt < 4; nt++) {
            int c = wn*32 + nt*8 + tig*2;
            float* dst = av + (size_t)(b*T_ + r)*D_ + h*HS_ + c;
            float* o = acc_o[mt][nt];
            float2 sv0 = *(const float2*)(suf0 + c);
            float2 sv1 = *(const float2*)(suf1 + c);
            *(float2*)dst = make_float2(
                tf32r(fmaf(wmr[mt][0], sv0.x, o[0]*oscale[mt][0])),
                tf32r(fmaf(wmr[mt][0], sv0.y, o[1]*oscale[mt][0])));
            *(float2*)(dst + 8*D_) = make_float2(
                tf32r(fmaf(wmr[mt][1], sv1.x, o[2]*oscale[mt][1])),
                tf32r(fmaf(wmr[mt][1], sv1.y, o[3]*oscale[mt][1])));
        }
    }
}

// ---------------- parallel V suffix scan ----------------
__global__ void suffixv_kernel(const float* __restrict__ vT, float* __restrict__ suf)
{
    int gw   = blockIdx.x * 8 + (threadIdx.x >> 5);
    int lane = threadIdx.x & 31;
    int e  = gw >> 2;
    int b  = gw & 3;
    int bh = b * H_ + (e >> 6);
    int ep = e & 63;
    const float* src = vT + (size_t)e * BT_ + b * T_;
    float* dst = suf + (size_t)bh * T_ * HS_ + ep;

    float carry = 0.f;
    for (int j = 31; j >= 0; j--) {
        int t = j*32 + lane;
        float v = src[t];
        float s = v;
        #pragma unroll
        for (int off = 1; off < 32; off <<= 1) {
            float o = __shfl_down_sync(0xffffffffu, s, off);
            if (lane + off < 32) s += o;
        }
        dst[(size_t)t * HS_] = s - v + carry;
        carry += __shfl_sync(0xffffffffu, s, 0);
    }
}

// ---------------- loss from LM-head partials ----------------
__global__ void lossrow2_kernel(const float2* __restrict__ part, int nch,
                                const float* __restrict__ logits,
                                const int* __restrict__ tgt,
                                float* __restrict__ rowloss)
{
    int row  = blockIdx.x;
    int lane = threadIdx.x;
    float m = -1e30f, s = 0.f;
    for (int i = lane; i < nch; i += 32) {
        float2 p = part[(size_t)row*nch + i];
        float M = fmaxf(m, p.x);
        s = s*__expf(m - M) + p.y*__expf(p.x - M);
        m = M;
    }
    #pragma unroll
    for (int off = 16; off > 0; off >>= 1) {
        float mo = __shfl_xor_sync(0xffffffffu, m, off);
        float so = __shfl_xor_sync(0xffffffffu, s, off);
        float M = fmaxf(m, mo);
        s = s*__expf(m - M) + so*__expf(mo - M);
        m = M;
    }
    if (lane == 0)
        rowloss[row] = m + logf(s) - logits[(size_t)row*V_ + tgt[row]];
}

__global__ void lossreduce_kernel(const float* __restrict__ rowloss,
                                  float* __restrict__ out)
{
    __shared__ float red[256];
    int tid = threadIdx.x;
    float s = 0.f;
    for (int i = tid; i < BT_; i += 256) s += rowloss[i];
    red[tid] = s; __syncthreads();
    for (int off = 128; off > 0; off >>= 1) {
        if (tid < off) red[tid] += red[tid+off];
        __syncthreads();
    }
    if (tid == 0) out[0] = red[0] / (float)BT_;
}

// ---------------- host ----------------
static float* sym(const void* s)
{
    void* p = nullptr;
    cudaGetSymbolAddress(&p, s);
    return (float*)p;
}

struct GemmArgs {
    const float *A, *B; float* C; const float* bias;
    int M, N, K, lda, ldb, ldc;
    bool acc, relu, round;
    float2* lsepart;
    int Z, zdiv;
    long long sAd, sAm, sBd, sBm, sCd, sCm;
};

static void gemm128x128(const GemmArgs& g)
{
    dim3 grid(g.N / 128, g.M / 128, g.Z);
    ntgemm_kernel<128,128,64,32><<<grid, 256>>>(
        g.A, g.B, g.C, g.bias, g.K, g.lda, g.ldb, g.ldc,
        g.acc, g.relu, g.round, g.lsepart, g.zdiv,
        g.sAd, g.sAm, g.sBd, g.sBm, g.sCd, g.sCm);
}

static void transpose(const float* in, float* out, int R, int C,
                      int ldi, int ldo, int Z, int zdiv, int roundout,
                      long long sId, long long sIm,
                      long long sOd, long long sOm)
{
    dim3 grid(C / 32, R / 32, Z);
    transpose_kernel<<<grid, dim3(32, 8)>>>(in, out, ldi, ldo, zdiv, roundout,
                                            sId, sIm, sOd, sOm);
}

extern "C" void kernel_launch(void* const* d_in, const int* in_sizes, int n_in,
                              void* d_out, int out_size)
{
    const int*   token_ids = (const int*)d_in[0];
    const int*   targets   = (const int*)d_in[1];
    const float* tok_table = (const float*)d_in[2];
    const float* pos_table = (const float*)d_in[3];
    const float* ln1_g = (const float*)d_in[4];
    const float* ln1_b = (const float*)d_in[5];
    const float* Wq = (const float*)d_in[6];
    const float* Wk = (const float*)d_in[7];
    const float* Wv = (const float*)d_in[8];
    const float* Wo = (const float*)d_in[9];
    const float* ln2_g = (const float*)d_in[10];
    const float* ln2_b = (const float*)d_in[11];
    const float* W1 = (const float*)d_in[12];
    const float* b1 = (const float*)d_in[13];
    const float* W2 = (const float*)d_in[14];
    const float* b2 = (const float*)d_in[15];
    const float* lnf_g = (const float*)d_in[16];
    const float* lnf_b = (const float*)d_in[17];
    const float* Wlm = (const float*)d_in[18];
    const float* blm = (const float*)d_in[19];

    cudaFuncSetAttribute(attn_kernel,
                         cudaFuncAttributeMaxDynamicSharedMemorySize, AT_SMEM);

    float* x    = sym(g_x);
    float* h    = sym(g_h);
    float* qkv  = sym(g_qkv);
    float* wp   = sym(g_wpack);
    float* woT  = sym(g_woT);
    float* w1T  = sym(g_w1T);
    float* w2T  = sym(g_w2T);
    float* wlmT = sym(g_wlmT);
    float* vT   = sym(g_vT);
    float* av   = sym(g_av);
    float* ffn  = sym(g_ffn);
    float* sufv = sym(g_sufv);
    float2* lsp = (float2*)sym(g_lsepart);
    float* rl   = sym(g_rowloss);

    const long long NLOGITS = (long long)BT_ * V_;
    float* out = (float*)d_out;
    bool out_has_logits = ((long long)out_size >= NLOGITS);
    float* logits = out_has_logits ? out : sym(g_logits);

    // ---- launches 0-4: embed, QKV packs, first LN ----
    embed_kernel<<<(BT_*D_ + 255)/256, 256>>>(token_ids, tok_table, pos_table, x);   // 0
    for (int grp = 0; grp < 3; grp++) {                                              // 1-3
        const float* W = (grp == 0) ? Wq : (grp == 1) ? Wk : Wv;
        transpose(W, wp + (long long)grp*H_*HS_*D_, D_, HS_, HS_, D_,
                  L_*H_, H_, 1,
                  (long long)H_*D_*HS_, (long long)D_*HS_,
                  (long long)QKVW_*D_, (long long)HS_*D_);
    }
    ln_kernel<<<BT_/8, 256>>>(x, ln1_g, ln1_b, h);                                   // 4

    // ---- launch 5: QKV GEMM for layer 0 (ncu -s 5 profiles this) ----
    {
        GemmArgs g{h, wp, qkv, nullptr,
                   BT_, QKVW_, D_, D_, D_, QKVW_,
                   false, false, true, nullptr, 1, 1, 0,0,0,0,0,0};
        gemm128x128(g);
    }

    // ---- remaining weight packs (first consumed later than this point) ----
    transpose(Wo, woT, H_*HS_, D_, D_, H_*HS_, L_, 1, 1,
              (long long)H_*HS_*D_, 0, (long long)D_*H_*HS_, 0);
    transpose(W1, w1T, D_, DFF_, DFF_, D_, L_, 1, 1,
              (long long)D_*DFF_, 0, (long long)DFF_*D_, 0);
    transpose(W2, w2T, DFF_, D_, D_, DFF_, L_, 1, 1,
              (long long)DFF_*D_, 0, (long long)D_*DFF_, 0);
    transpose(Wlm, wlmT, D_, V_, V_, D_, 1, 1, 1, 0, 0, 0, 0);

    for (int l = 0; l < L_; l++) {
        if (l > 0) {
            ln_kernel<<<BT_/8, 256>>>(x, ln1_g + l*D_, ln1_b + l*D_, h);
            GemmArgs g{h, wp + (long long)l*QKVW_*D_, qkv, nullptr,
                       BT_, QKVW_, D_, D_, D_, QKVW_,
                       false, false, true, nullptr, 1, 1, 0,0,0,0,0,0};
            gemm128x128(g);
        }

        // V^T, suffix scan
        transpose(qkv + 2*H_*HS_, vT, BT_, D_, QKVW_, BT_, 1, 1, 0, 0, 0, 0, 0);
        suffixv_kernel<<<192, 256>>>(vT, sufv);

        // fused attention (+ suffix-V correction in epilogue)
        attn_kernel<<<dim3(B_*H_, T_/128), 256, AT_SMEM>>>(qkv, vT, sufv, av);

        // x += av @ Wo[l]
        {
            GemmArgs g{av, woT + (long long)l*D_*H_*HS_, x, nullptr,
                       BT_, D_, H_*HS_, H_*HS_, H_*HS_, D_,
                       true, false, false, nullptr, 1, 1, 0,0,0,0,0,0};
            gemm128x128(g);
        }

        ln_kernel<<<BT_/8, 256>>>(x, ln2_g + l*D_, ln2_b + l*D_, h);

        // ffn
        {
            GemmArgs g{h, w1T + (long long)l*DFF_*D_, ffn, b1 + l*DFF_,
                       BT_, DFF_, D_, D_, D_, DFF_,
                       false, true, true, nullptr, 1, 1, 0,0,0,0,0,0};
            gemm128x128(g);
        }
        {
            GemmArgs g{ffn, w2T + (long long)l*D_*DFF_, x, b2 + l*D_,
                       BT_, D_, DFF_, DFF_, DFF_, D_,
                       true, false, false, nullptr, 1, 1, 0,0,0,0,0,0};
            gemm128x128(g);
        }
    }

    ln_kernel<<<BT_/8, 256>>>(x, lnf_g, lnf_b, h);

    // LM head with fused LSE partials (250 chunks)
    {
        GemmArgs g{h, wlmT, logits, blm,
                   BT_, V_, D_, D_, D_, V_,
                   false, false, false, lsp, 1, 1, 0,0,0,0,0,0};
        gemm128x128(g);
    }

    lossrow2_kernel<<<BT_, 32>>>(lsp, NCH_, logits, targets, rl);
    if (out_has_logits && (long long)out_size > NLOGITS) {
        lossreduce_kernel<<<1, 256>>>(rl, out + NLOGITS);
    } else if (!out_has_logits && out_size >= 1) {
        lossreduce_kernel<<<1, 256>>>(rl, out);
    }
}

// round 16
// speedup vs baseline: 1.5481x; 1.0051x over previous
#include <cuda_runtime.h>
#include <cuda_bf16.h>
#include <math.h>
#include <stdint.h>

// Problem dims
#define B_  4
#define T_  1024
#define V_  32000
#define D_  384
#define H_  6
#define HS_ 64
#define L_  6
#define DFF_ 1536
#define BT_ (B_*T_)
#define QKVW_ (3*H_*HS_)   // 1152
#define NCH_ (V_/128)      // lsepart capacity
#define EPS_ 1e-5f
#define SCALE_ 0.125f

// ---------------- static scratch ----------------
__device__ float g_x[BT_*D_];
__device__ float g_h[BT_*D_];
__device__ float g_qkv[(size_t)BT_*QKVW_];
__device__ float g_wpack[(size_t)L_*QKVW_*D_];
__device__ float g_woT[(size_t)L_*D_*(H_*HS_)];
__device__ float g_w1T[(size_t)L_*DFF_*D_];
__device__ float g_w2T[(size_t)L_*D_*DFF_];
__device__ float g_wlmT[(size_t)V_*D_];
__device__ float g_vT[(size_t)D_*BT_];
__device__ float g_av[BT_*D_];
__device__ float g_ffn[BT_*DFF_];
__device__ float g_sufv[(size_t)B_*H_*T_*HS_];
__device__ float2 g_lsepart[(size_t)BT_*NCH_];
__device__ float g_rowloss[BT_];
__device__ float g_logits[(size_t)BT_*V_];

// ---------------- tf32 helper ----------------
__device__ __forceinline__ float tf32r(float x)
{
    asm("cvt.rna.tf32.f32 %0, %0;" : "+f"(x));
    return x;
}
#define FU(x) __float_as_uint(x)

// ---------------- embed ----------------
__global__ void embed_kernel(const int* __restrict__ tok,
                             const float* __restrict__ tt,
                             const float* __restrict__ pt,
                             float* __restrict__ x)
{
    int idx = blockIdx.x * blockDim.x + threadIdx.x;
    if (idx >= BT_*D_) return;
    int bt = idx / D_;
    int d  = idx - bt * D_;
    int t  = bt % T_;
    x[idx] = tt[(size_t)tok[bt] * D_ + d] + pt[t * D_ + d];
}

// ---------------- tiled transpose ----------------
__global__ void transpose_kernel(const float* __restrict__ in,
                                 float* __restrict__ out,
                                 int ldi, int ldo, int zdiv, int roundout,
                                 long long sId, long long sIm,
                                 long long sOd, long long sOm)
{
    __shared__ float tile[32][33];
    int z  = blockIdx.z;
    int zq = z / zdiv;
    int zr = z - zq * zdiv;
    in  += zq * sId + (long long)zr * sIm;
    out += zq * sOd + (long long)zr * sOm;

    int r0 = blockIdx.y * 32;
    int c0 = blockIdx.x * 32;
    int tx = threadIdx.x, ty = threadIdx.y;
    #pragma unroll
    for (int j = 0; j < 4; j++)
        tile[ty + 8*j][tx] = in[(size_t)(r0 + ty + 8*j) * ldi + c0 + tx];
    __syncthreads();
    #pragma unroll
    for (int j = 0; j < 4; j++) {
        float v = tile[tx][ty + 8*j];
        if (roundout) v = tf32r(v);
        out[(size_t)(c0 + ty + 8*j) * ldo + r0 + tx] = v;
    }
}

// ---------------- layernorm: warp per row ----------------
__global__ void ln_kernel(const float* __restrict__ x,
                          const float* __restrict__ g,
                          const float* __restrict__ b,
                          float* __restrict__ y)
{
    int warp = threadIdx.x >> 5;
    int lane = threadIdx.x & 31;
    size_t row = (size_t)blockIdx.x * 8 + warp;
    const float4* xr = (const float4*)(x + row * D_);
    const float4* g4 = (const float4*)g;
    const float4* b4 = (const float4*)b;
    float4* yr = (float4*)(y + row * D_);

    float4 v[3];
    float s = 0.f, q = 0.f;
    #pragma unroll
    for (int i = 0; i < 3; i++) {
        v[i] = xr[lane + i*32];
        s += v[i].x + v[i].y + v[i].z + v[i].w;
        q += v[i].x*v[i].x + v[i].y*v[i].y + v[i].z*v[i].z + v[i].w*v[i].w;
    }
    #pragma unroll
    for (int off = 16; off > 0; off >>= 1) {
        s += __shfl_xor_sync(0xffffffffu, s, off);
        q += __shfl_xor_sync(0xffffffffu, q, off);
    }
    float mean = s * (1.0f / D_);
    float var  = q * (1.0f / D_) - mean * mean;
    float inv  = rsqrtf(var + EPS_);
    #pragma unroll
    for (int i = 0; i < 3; i++) {
        float4 gg = g4[lane + i*32];
        float4 bb = b4[lane + i*32];
        float4 o;
        o.x = tf32r((v[i].x - mean) * inv * gg.x + bb.x);
        o.y = tf32r((v[i].y - mean) * inv * gg.y + bb.y);
        o.z = tf32r((v[i].z - mean) * inv * gg.z + bb.z);
        o.w = tf32r((v[i].w - mean) * inv * gg.w + bb.w);
        yr[lane + i*32] = o;
    }
}

__device__ __forceinline__ void mma_tf32(float c[4],
    uint32_t a0, uint32_t a1, uint32_t a2, uint32_t a3,
    uint32_t b0, uint32_t b1)
{
    asm volatile(
        "mma.sync.aligned.m16n8k8.row.col.f32.tf32.tf32.f32 "
        "{%0,%1,%2,%3}, {%4,%5,%6,%7}, {%8,%9}, {%0,%1,%2,%3};"
        : "+f"(c[0]), "+f"(c[1]), "+f"(c[2]), "+f"(c[3])
        : "r"(a0), "r"(a1), "r"(a2), "r"(a3), "r"(b0), "r"(b1));
}

// ---------------- NT tensor-core GEMM, cp.async 4-stage (dynamic smem, occ 2) ----
template<int BM, int BN, int WM, int WN>
__global__ void __launch_bounds__(256, 2)
ntgemm_kernel(const float* __restrict__ A,
              const float* __restrict__ B,
              float* __restrict__ C,
              const float* __restrict__ bias,
              int K, int lda, int ldb, int ldc,
              int accumulate, int relu, int roundout,
              float2* lsepart, int zdiv,
              long long sAd, long long sAm,
              long long sBd, long long sBm,
              long long sCd, long long sCm)
{
    constexpr int BK = 16;
    constexpr int NSTAGE = 4;
    constexpr int MT = WM / 16;
    constexpr int NT = WN / 8;
    constexpr int WARPS_N = BN / WN;
    static_assert((BM/WM) * (BN/WN) == 8, "8 warps");
    constexpr int APT = BM / 64;
    constexpr int BPT = BN / 64;

    extern __shared__ float dynsm[];
    float (*As)[BM][BK] = (float(*)[BM][BK])dynsm;
    float (*Bs)[BN][BK] = (float(*)[BN][BK])(dynsm + NSTAGE*BM*BK);

    const int row0 = blockIdx.y * BM;
    const int col0 = blockIdx.x * BN;

    int z  = blockIdx.z;
    int zq = z / zdiv;
    int zr = z - zq * zdiv;
    A += zq * sAd + (long long)zr * sAm;
    B += zq * sBd + (long long)zr * sBm;
    C += zq * sCd + (long long)zr * sCm;

    const int tid  = threadIdx.x;
    const int lane = tid & 31;
    const int wid  = tid >> 5;
    const int wm   = wid / WARPS_N;
    const int wn   = wid % WARPS_N;
    const int gid  = lane >> 2;
    const int tig4 = (lane & 3) * 4;

    float acc[MT][NT][4] = {};

    const int s_row = tid >> 2;
    const int s_kq  = (tid & 3) * 4;

    auto ISSUE = [&](int stage, int k0) {
        if (k0 < K) {
            #pragma unroll
            for (int i = 0; i < APT; i++) {
                uint32_t dst = (uint32_t)__cvta_generic_to_shared(&As[stage][s_row + i*64][s_kq]);
                const float* src = A + (size_t)(row0 + s_row + i*64) * lda + k0 + s_kq;
                asm volatile("cp.async.cg.shared.global [%0], [%1], 16;\n" :: "r"(dst), "l"(src));
            }
            #pragma unroll
            for (int i = 0; i < BPT; i++) {
                uint32_t dst = (uint32_t)__cvta_generic_to_shared(&Bs[stage][s_row + i*64][s_kq]);
                const float* src = B + (size_t)(col0 + s_row + i*64) * ldb + k0 + s_kq;
                asm volatile("cp.async.cg.shared.global [%0], [%1], 16;\n" :: "r"(dst), "l"(src));
            }
        }
        asm volatile("cp.async.commit_group;\n");
    };

    auto COMPUTE = [&](int buf) {
        float4 bq[NT];
        #pragma unroll
        for (int nt = 0; nt < NT; nt++)
            bq[nt] = *(const float4*)&Bs[buf][wn*WN + nt*8 + gid][tig4];
        #pragma unroll
        for (int mt = 0; mt < MT; mt++) {
            int m0 = wm*WM + mt*16 + gid;
            float4 a0 = *(const float4*)&As[buf][m0    ][tig4];
            float4 a1 = *(const float4*)&As[buf][m0 + 8][tig4];
            #pragma unroll
            for (int nt = 0; nt < NT; nt++) {
                mma_tf32(acc[mt][nt], FU(a0.x), FU(a1.x), FU(a0.y), FU(a1.y),
                         FU(bq[nt].x), FU(bq[nt].y));
                mma_tf32(acc[mt][nt], FU(a0.z), FU(a1.z), FU(a0.w), FU(a1.w),
                         FU(bq[nt].z), FU(bq[nt].w));
            }
        }
    };

    ISSUE(0, 0);
    ISSUE(1, BK);
    ISSUE(2, 2*BK);

    const int niter = K / BK;
    for (int it = 0; it < niter; it++) {
        asm volatile("cp.async.wait_group 2;\n");
        __syncthreads();
        ISSUE((it + NSTAGE - 1) % NSTAGE, (it + NSTAGE - 1) * BK);
        COMPUTE(it % NSTAGE);
    }

    if (lsepart) {
        asm volatile("cp.async.wait_group 0;\n");
        __syncthreads();
        float2* lse_s = (float2*)dynsm;
        #pragma unroll
        for (int mt = 0; mt < MT; mt++) {
            float va[2][NT*2];
            #pragma unroll
            for (int nt = 0; nt < NT; nt++) {
                int r = row0 + wm*WM + mt*16 + gid;
                int c = col0 + wn*WN + nt*8 + (lane & 3)*2;
                float2 v0 = make_float2(acc[mt][nt][0], acc[mt][nt][1]);
                float2 v1 = make_float2(acc[mt][nt][2], acc[mt][nt][3]);
                if (bias) {
                    float2 bb = *(const float2*)(bias + c);
                    v0.x += bb.x; v0.y += bb.y;
                    v1.x += bb.x; v1.y += bb.y;
                }
                *(float2*)(C + (size_t)r * ldc + c)     = v0;
                *(float2*)(C + (size_t)(r+8) * ldc + c) = v1;
                va[0][nt*2] = v0.x; va[0][nt*2+1] = v0.y;
                va[1][nt*2] = v1.x; va[1][nt*2+1] = v1.y;
            }
            #pragma unroll
            for (int hf = 0; hf < 2; hf++) {
                float mx = va[hf][0];
                #pragma unroll
                for (int j = 1; j < NT*2; j++) mx = fmaxf(mx, va[hf][j]);
                float sm = 0.f;
                #pragma unroll
                for (int j = 0; j < NT*2; j++) sm += __expf(va[hf][j] - mx);
                #pragma unroll
                for (int off = 1; off <= 2; off <<= 1) {
                    float mo = __shfl_xor_sync(0xffffffffu, mx, off);
                    float so = __shfl_xor_sync(0xffffffffu, sm, off);
                    float M = fmaxf(mx, mo);
                    sm = sm*__expf(mx - M) + so*__expf(mo - M);
                    mx = M;
                }
                if ((lane & 3) == 0) {
                    int rl = wm*WM + mt*16 + gid + hf*8;
                    lse_s[rl*WARPS_N + wn] = make_float2(mx, sm);
                }
            }
        }
        __syncthreads();
        if (tid < BM) {
            float2 a = lse_s[tid*WARPS_N];
            #pragma unroll
            for (int w = 1; w < WARPS_N; w++) {
                float2 b = lse_s[tid*WARPS_N + w];
                float M = fmaxf(a.x, b.x);
                a = make_float2(M, a.y*__expf(a.x - M) + b.y*__expf(b.x - M));
            }
            lsepart[(size_t)(row0 + tid) * gridDim.x + blockIdx.x] = a;
        }
        return;
    }

    #pragma unroll
    for (int mt = 0; mt < MT; mt++) {
        #pragma unroll
        for (int nt = 0; nt < NT; nt++) {
            int r = row0 + wm*WM + mt*16 + gid;
            int c = col0 + wn*WN + nt*8 + (lane & 3)*2;
            float2 v0 = make_float2(acc[mt][nt][0], acc[mt][nt][1]);
            float2 v1 = make_float2(acc[mt][nt][2], acc[mt][nt][3]);
            if (bias) {
                float2 bb = *(const float2*)(bias + c);
                v0.x += bb.x; v0.y += bb.y;
                v1.x += bb.x; v1.y += bb.y;
            }
            float* p0 = C + (size_t)r * ldc + c;
            float* p1 = C + (size_t)(r+8) * ldc + c;
            if (accumulate) {
                float2 c0 = *(const float2*)p0;
                float2 c1 = *(const float2*)p1;
                v0.x += c0.x; v0.y += c0.y;
                v1.x += c1.x; v1.y += c1.y;
            }
            if (relu) {
                v0.x = fmaxf(v0.x, 0.f); v0.y = fmaxf(v0.y, 0.f);
                v1.x = fmaxf(v1.x, 0.f); v1.y = fmaxf(v1.y, 0.f);
            }
            if (roundout) {
                v0.x = tf32r(v0.x); v0.y = tf32r(v0.y);
                v1.x = tf32r(v1.x); v1.y = tf32r(v1.y);
            }
            *(float2*)p0 = v0;
            *(float2*)p1 = v1;
        }
    }
}
#define GEMM_DSMEM (4*(128+128)*16*4)

// ---------------- fused attention, K-prefetched ----------------
#define AT_SMEM ((128*64 + 64*64 + 64*64 + 128*64 + 256 + 256)*4)

__global__ void __launch_bounds__(256, 2)
attn_kernel(const float* __restrict__ qkv,
            const float* __restrict__ vT,
            const float* __restrict__ sufv,
            float* __restrict__ av)
{
    extern __shared__ float sm[];
    float* Qs   = sm;
    float* Ks   = Qs + 128*64;
    float* Vs   = Ks + 64*64;
    float* Ps   = Vs + 64*64;
    float* rmax = Ps + 128*64;
    float* rsum = rmax + 256;

    const int bh = blockIdx.x;
    const int b = bh / H_, h = bh - b*H_;
    const int row0 = (gridDim.y - 1 - blockIdx.y) * 128;

    const int tid  = threadIdx.x;
    const int lane = tid & 31;
    const int wid  = tid >> 5;
    const int wm   = wid >> 1;
    const int wn   = wid & 1;
    const int gid  = lane >> 2;
    const int tig  = lane & 3;

    const float* kbase0 = qkv + (size_t)(b*T_) * QKVW_ + H_*HS_ + h*HS_;
    const float* vbase0 = vT + (size_t)(h*HS_) * BT_ + b*T_;

    auto ISSUE_K = [&](int j) {
        const float* kb = kbase0 + (size_t)(j*64) * QKVW_;
        #pragma unroll
        for (int i = 0; i < 4; i++) {
            int idx = tid + i*256;
            int r = idx >> 4, c = idx & 15;
            int cc = (c + ((r & 3) << 2)) & 15;
            uint32_t dk = (uint32_t)__cvta_generic_to_shared(Ks + r*64 + cc*4);
            asm volatile("cp.async.cg.shared.global [%0], [%1], 16;\n"
                         :: "r"(dk), "l"(kb + (size_t)r * QKVW_ + c*4));
        }
        asm volatile("cp.async.commit_group;\n");
    };
    auto ISSUE_V = [&](int j) {
        const float* vb = vbase0 + j*64;
        #pragma unroll
        for (int i = 0; i < 4; i++) {
            int idx = tid + i*256;
            int r = idx >> 4, c = idx & 15;
            int cc = (c + ((r & 3) << 2)) & 15;
            uint32_t dv = (uint32_t)__cvta_generic_to_shared(Vs + r*64 + cc*4);
            asm volatile("cp.async.cg.shared.global [%0], [%1], 16;\n"
                         :: "r"(dv), "l"(vb + (size_t)r * BT_ + c*4));
        }
        asm volatile("cp.async.commit_group;\n");
    };

    // Q load + K(0) prefetch
    {
        const float* qbase = qkv + (size_t)(b*T_ + row0) * QKVW_ + h*HS_;
        #pragma unroll
        for (int i = 0; i < 8; i++) {
            int idx = tid + i*256;
            int r = idx >> 4, c = idx & 15;
            int cc = (c + ((r & 3) << 2)) & 15;
            uint32_t dst = (uint32_t)__cvta_generic_to_shared(Qs + r*64 + cc*4);
            const float* src = qbase + (size_t)r * QKVW_ + c*4;
            asm volatile("cp.async.cg.shared.global [%0], [%1], 16;\n" :: "r"(dst), "l"(src));
        }
        asm volatile("cp.async.commit_group;\n");
    }
    ISSUE_K(0);

    float m_run[2][2], s_run[2][2];
    float acc_o[2][4][4] = {};
    #pragma unroll
    for (int mt = 0; mt < 2; mt++)
        #pragma unroll
        for (int k = 0; k < 2; k++) { m_run[mt][k] = -1e30f; s_run[mt][k] = 0.f; }

    const int jmax = row0/64 + 2;

    for (int j = 0; j < jmax; j++) {
        __syncthreads();           // Vs free (prev P@V done)
        ISSUE_V(j);
        asm volatile("cp.async.wait_group 0;\n");
        __syncthreads();

        // ---- S = Q @ K^T ----
        float acc_s[2][4][4] = {};
        #pragma unroll
        for (int ks = 0; ks < 4; ks++) {
            int fidx = ((ks*16 + tig*4) + ((gid & 3) << 4)) & 63;
            float4 bq[4];
            #pragma unroll
            for (int nt = 0; nt < 4; nt++) {
                int n0 = wn*32 + nt*8 + gid;
                bq[nt] = *(const float4*)&Ks[n0*64 + fidx];
            }
            #pragma unroll
            for (int mt = 0; mt < 2; mt++) {
                int m0 = wm*32 + mt*16 + gid;
                float4 a0 = *(const float4*)&Qs[m0*64 + fidx];
                float4 a1 = *(const float4*)&Qs[(m0+8)*64 + fidx];
                #pragma unroll
                for (int nt = 0; nt < 4; nt++) {
                    mma_tf32(acc_s[mt][nt], FU(a0.x), FU(a1.x), FU(a0.y), FU(a1.y),
                             FU(bq[nt].x), FU(bq[nt].y));
                    mma_tf32(acc_s[mt][nt], FU(a0.z), FU(a1.z), FU(a0.w), FU(a1.w),
                             FU(bq[nt].z), FU(bq[nt].w));
                }
            }
        }

        // ---- scale + mask + tile max ----
        float tmax[2][2];
        #pragma unroll
        for (int mt = 0; mt < 2; mt++) {
            int t0 = row0 + wm*32 + mt*16 + gid;
            int t1 = t0 + 8;
            tmax[mt][0] = -1e30f; tmax[mt][1] = -1e30f;
            #pragma unroll
            for (int nt = 0; nt < 4; nt++) {
                int c0 = j*64 + wn*32 + nt*8 + tig*2;
                float* a = acc_s[mt][nt];
                a[0] = (c0   <= t0) ? a[0]*SCALE_ : -1e30f;
                a[1] = (c0+1 <= t0) ? a[1]*SCALE_ : -1e30f;
                a[2] = (c0   <= t1) ? a[2]*SCALE_ : -1e30f;
                a[3] = (c0+1 <= t1) ? a[3]*SCALE_ : -1e30f;
                tmax[mt][0] = fmaxf(tmax[mt][0], fmaxf(a[0], a[1]));
                tmax[mt][1] = fmaxf(tmax[mt][1], fmaxf(a[2], a[3]));
            }
            #pragma unroll
            for (int off = 1; off <= 2; off <<= 1) {
                tmax[mt][0] = fmaxf(tmax[mt][0], __shfl_xor_sync(0xffffffffu, tmax[mt][0], off));
                tmax[mt][1] = fmaxf(tmax[mt][1], __shfl_xor_sync(0xffffffffu, tmax[mt][1], off));
            }
            if (tig == 0) {
                int rl = wm*32 + mt*16 + gid;
                rmax[rl*2 + wn]     = tmax[mt][0];
                rmax[(rl+8)*2 + wn] = tmax[mt][1];
            }
        }
        __syncthreads();           // all S-GEMM Ks reads complete

        if (j + 1 < jmax) ISSUE_K(j + 1);   // prefetch next K into Ks

        float alpha[2][2], psum[2][2];
        #pragma unroll
        for (int mt = 0; mt < 2; mt++) {
            #pragma unroll
            for (int k = 0; k < 2; k++) {
                int rl = wm*32 + mt*16 + gid + k*8;
                float tm = fmaxf(rmax[rl*2], rmax[rl*2+1]);
                float mn = fmaxf(m_run[mt][k], tm);
                alpha[mt][k] = __expf(m_run[mt][k] - mn);
                m_run[mt][k] = mn;
                psum[mt][k] = 0.f;
            }
        }
        #pragma unroll
        for (int mt = 0; mt < 2; mt++) {
            int r0l = wm*32 + mt*16 + gid;
            int rot = (r0l & 3) << 4;
            #pragma unroll
            for (int nt = 0; nt < 4; nt++) {
                float* a = acc_s[mt][nt];
                float p0 = __expf(a[0] - m_run[mt][0]);
                float p1 = __expf(a[1] - m_run[mt][0]);
                float p2 = __expf(a[2] - m_run[mt][1]);
                float p3 = __expf(a[3] - m_run[mt][1]);
                psum[mt][0] += p0 + p1;
                psum[mt][1] += p2 + p3;
                int c = wn*32 + nt*8 + tig*2;
                int f = (c + rot) & 63;
                *(float2*)&Ps[r0l*64 + f]     = make_float2(tf32r(p0), tf32r(p1));
                *(float2*)&Ps[(r0l+8)*64 + f] = make_float2(tf32r(p2), tf32r(p3));
                float* o = acc_o[mt][nt];
                o[0] *= alpha[mt][0]; o[1] *= alpha[mt][0];
                o[2] *= alpha[mt][1]; o[3] *= alpha[mt][1];
            }
            #pragma unroll
            for (int off = 1; off <= 2; off <<= 1) {
                psum[mt][0] += __shfl_xor_sync(0xffffffffu, psum[mt][0], off);
                psum[mt][1] += __shfl_xor_sync(0xffffffffu, psum[mt][1], off);
            }
            if (tig == 0) {
                rsum[r0l*2 + wn]     = psum[mt][0];
                rsum[(r0l+8)*2 + wn] = psum[mt][1];
            }
        }
        __syncthreads();
        #pragma unroll
        for (int mt = 0; mt < 2; mt++) {
            #pragma unroll
            for (int k = 0; k < 2; k++) {
                int rl = wm*32 + mt*16 + gid + k*8;
                float ts = rsum[rl*2] + rsum[rl*2+1];
                s_run[mt][k] = s_run[mt][k]*alpha[mt][k] + ts;
            }
        }

        // ---- O += P @ V ----
        #pragma unroll
        for (int ks = 0; ks < 4; ks++) {
            int fidx = ((ks*16 + tig*4) + ((gid & 3) << 4)) & 63;
            float4 bq[4];
            #pragma unroll
            for (int nt = 0; nt < 4; nt++) {
                int e0 = wn*32 + nt*8 + gid;
                bq[nt] = *(const float4*)&Vs[e0*64 + fidx];
            }
            #pragma unroll
            for (int mt = 0; mt < 2; mt++) {
                int m0 = wm*32 + mt*16 + gid;
                float4 a0 = *(const float4*)&Ps[m0*64 + fidx];
                float4 a1 = *(const float4*)&Ps[(m0+8)*64 + fidx];
                #pragma unroll
                for (int nt = 0; nt < 4; nt++) {
                    mma_tf32(acc_o[mt][nt], FU(a0.x), FU(a1.x), FU(a0.y), FU(a1.y),
                             FU(bq[nt].x), FU(bq[nt].y));
                    mma_tf32(acc_o[mt][nt], FU(a0.z), FU(a1.z), FU(a0.w), FU(a1.w),
                             FU(bq[nt].z), FU(bq[nt].w));
                }
            }
        }
    }

    float oscale[2][2], wmr[2][2];
    #pragma unroll
    for (int mt = 0; mt < 2; mt++) {
        #pragma unroll
        for (int k = 0; k < 2; k++) {
            int t = row0 + wm*32 + mt*16 + gid + k*8;
            float mr = m_run[mt][k], sr = s_run[mt][k];
            int count = T_ - 1 - t;
            float mf = (count > 0) ? fmaxf(mr, 0.f) : mr;
            float emm = __expf(mr - mf);
            float denom = sr * emm + (float)count * __expf(-mf);
            oscale[mt][k] = emm / denom;
            wmr[mt][k]    = __expf(-mf) / denom;
        }
    }
    #pragma unroll
    for (int mt = 0; mt < 2; mt++) {
        int r = row0 + wm*32 + mt*16 + gid;
        const float* suf0 = sufv + ((size_t)bh*T_ + r) * HS_;
        const float* suf1 = suf0 + (size_t)8 * HS_;
        #pragma unroll
        for (int nt = 0; nt < 4; nt++) {
            int c = wn*32 + nt*8 + tig*2;
            float* dst = av + (size_t)(b*T_ + r)*D_ + h*HS_ + c;
            float* o = acc_o[mt][nt];
            float2 sv0 = *(const float2*)(suf0 + c);
            float2 sv1 = *(const float2*)(suf1 + c);
            *(float2*)dst = make_float2(
                tf32r(fmaf(wmr[mt][0], sv0.x, o[0]*oscale[mt][0])),
                tf32r(fmaf(wmr[mt][0], sv0.y, o[1]*oscale[mt][0])));
            *(float2*)(dst + 8*D_) = make_float2(
                tf32r(fmaf(wmr[mt][1], sv1.x, o[2]*oscale[mt][1])),
                tf32r(fmaf(wmr[mt][1], sv1.y, o[3]*oscale[mt][1])));
        }
    }
}

// ---------------- parallel V suffix scan ----------------
__global__ void suffixv_kernel(const float* __restrict__ vT, float* __restrict__ suf)
{
    int gw   = blockIdx.x * 8 + (threadIdx.x >> 5);
    int lane = threadIdx.x & 31;
    int e  = gw >> 2;
    int b  = gw & 3;
    int bh = b * H_ + (e >> 6);
    int ep = e & 63;
    const float* src = vT + (size_t)e * BT_ + b * T_;
    float* dst = suf + (size_t)bh * T_ * HS_ + ep;

    float carry = 0.f;
    for (int j = 31; j >= 0; j--) {
        int t = j*32 + lane;
        float v = src[t];
        float s = v;
        #pragma unroll
        for (int off = 1; off < 32; off <<= 1) {
            float o = __shfl_down_sync(0xffffffffu, s, off);
            if (lane + off < 32) s += o;
        }
        dst[(size_t)t * HS_] = s - v + carry;
        carry += __shfl_sync(0xffffffffu, s, 0);
    }
}

// ---------------- loss from LM-head partials (8 rows / block) ----------------
__global__ void lossrow2_kernel(const float2* __restrict__ part, int nch,
                                const float* __restrict__ logits,
                                const int* __restrict__ tgt,
                                float* __restrict__ rowloss)
{
    int row  = blockIdx.x * 8 + (threadIdx.x >> 5);
    int lane = threadIdx.x & 31;
    float m = -1e30f, s = 0.f;
    for (int i = lane; i < nch; i += 32) {
        float2 p = part[(size_t)row*nch + i];
        float M = fmaxf(m, p.x);
        s = s*__expf(m - M) + p.y*__expf(p.x - M);
        m = M;
    }
    #pragma unroll
    for (int off = 16; off > 0; off >>= 1) {
        float mo = __shfl_xor_sync(0xffffffffu, m, off);
        float so = __shfl_xor_sync(0xffffffffu, s, off);
        float M = fmaxf(m, mo);
        s = s*__expf(m - M) + so*__expf(mo - M);
        m = M;
    }
    if (lane == 0)
        rowloss[row] = m + logf(s) - logits[(size_t)row*V_ + tgt[row]];
}

__global__ void lossreduce_kernel(const float* __restrict__ rowloss,
                                  float* __restrict__ out)
{
    __shared__ float red[256];
    int tid = threadIdx.x;
    float s = 0.f;
    for (int i = tid; i < BT_; i += 256) s += rowloss[i];
    red[tid] = s; __syncthreads();
    for (int off = 128; off > 0; off >>= 1) {
        if (tid < off) red[tid] += red[tid+off];
        __syncthreads();
    }
    if (tid == 0) out[0] = red[0] / (float)BT_;
}

// ---------------- host ----------------
static float* sym(const void* s)
{
    void* p = nullptr;
    cudaGetSymbolAddress(&p, s);
    return (float*)p;
}

struct GemmArgs {
    const float *A, *B; float* C; const float* bias;
    int M, N, K, lda, ldb, ldc;
    bool acc, relu, round;
    float2* lsepart;
    int Z, zdiv;
    long long sAd, sAm, sBd, sBm, sCd, sCm;
};

static void gemm128x128(const GemmArgs& g)
{
    dim3 grid(g.N / 128, g.M / 128, g.Z);
    ntgemm_kernel<128,128,64,32><<<grid, 256, GEMM_DSMEM>>>(
        g.A, g.B, g.C, g.bias, g.K, g.lda, g.ldb, g.ldc,
        g.acc, g.relu, g.round, g.lsepart, g.zdiv,
        g.sAd, g.sAm, g.sBd, g.sBm, g.sCd, g.sCm);
}

static void transpose(const float* in, float* out, int R, int C,
                      int ldi, int ldo, int Z, int zdiv, int roundout,
                      long long sId, long long sIm,
                      long long sOd, long long sOm)
{
    dim3 grid(C / 32, R / 32, Z);
    transpose_kernel<<<grid, dim3(32, 8)>>>(in, out, ldi, ldo, zdiv, roundout,
                                            sId, sIm, sOd, sOm);
}

extern "C" void kernel_launch(void* const* d_in, const int* in_sizes, int n_in,
                              void* d_out, int out_size)
{
    const int*   token_ids = (const int*)d_in[0];
    const int*   targets   = (const int*)d_in[1];
    const float* tok_table = (const float*)d_in[2];
    const float* pos_table = (const float*)d_in[3];
    const float* ln1_g = (const float*)d_in[4];
    const float* ln1_b = (const float*)d_in[5];
    const float* Wq = (const float*)d_in[6];
    const float* Wk = (const float*)d_in[7];
    const float* Wv = (const float*)d_in[8];
    const float* Wo = (const float*)d_in[9];
    const float* ln2_g = (const float*)d_in[10];
    const float* ln2_b = (const float*)d_in[11];
    const float* W1 = (const float*)d_in[12];
    const float* b1 = (const float*)d_in[13];
    const float* W2 = (const float*)d_in[14];
    const float* b2 = (const float*)d_in[15];
    const float* lnf_g = (const float*)d_in[16];
    const float* lnf_b = (const float*)d_in[17];
    const float* Wlm = (const float*)d_in[18];
    const float* blm = (const float*)d_in[19];

    cudaFuncSetAttribute(attn_kernel,
                         cudaFuncAttributeMaxDynamicSharedMemorySize, AT_SMEM);
    cudaFuncSetAttribute(ntgemm_kernel<128,128,64,32>,
                         cudaFuncAttributeMaxDynamicSharedMemorySize, GEMM_DSMEM);

    float* x    = sym(g_x);
    float* h    = sym(g_h);
    float* qkv  = sym(g_qkv);
    float* wp   = sym(g_wpack);
    float* woT  = sym(g_woT);
    float* w1T  = sym(g_w1T);
    float* w2T  = sym(g_w2T);
    float* wlmT = sym(g_wlmT);
    float* vT   = sym(g_vT);
    float* av   = sym(g_av);
    float* ffn  = sym(g_ffn);
    float* sufv = sym(g_sufv);
    float2* lsp = (float2*)sym(g_lsepart);
    float* rl   = sym(g_rowloss);

    const long long NLOGITS = (long long)BT_ * V_;
    float* out = (float*)d_out;
    bool out_has_logits = ((long long)out_size >= NLOGITS);
    float* logits = out_has_logits ? out : sym(g_logits);

    // ---- embed + weight packs ----
    embed_kernel<<<(BT_*D_ + 255)/256, 256>>>(token_ids, tok_table, pos_table, x);
    for (int grp = 0; grp < 3; grp++) {
        const float* W = (grp == 0) ? Wq : (grp == 1) ? Wk : Wv;
        transpose(W, wp + (long long)grp*H_*HS_*D_, D_, HS_, HS_, D_,
                  L_*H_, H_, 1,
                  (long long)H_*D_*HS_, (long long)D_*HS_,
                  (long long)QKVW_*D_, (long long)HS_*D_);
    }
    transpose(Wo, woT, H_*HS_, D_, D_, H_*HS_, L_, 1, 1,
              (long long)H_*HS_*D_, 0, (long long)D_*H_*HS_, 0);
    transpose(W1, w1T, D_, DFF_, DFF_, D_, L_, 1, 1,
              (long long)D_*DFF_, 0, (long long)DFF_*D_, 0);
    transpose(W2, w2T, DFF_, D_, D_, DFF_, L_, 1, 1,
              (long long)DFF_*D_, 0, (long long)D_*DFF_, 0);
    transpose(Wlm, wlmT, D_, V_, V_, D_, 1, 1, 1, 0, 0, 0, 0);

    for (int l = 0; l < L_; l++) {
        ln_kernel<<<BT_/8, 256>>>(x, ln1_g + l*D_, ln1_b + l*D_, h);

        // fused QKV (rounded)
        {
            GemmArgs g{h, wp + (long long)l*QKVW_*D_, qkv, nullptr,
                       BT_, QKVW_, D_, D_, D_, QKVW_,
                       false, false, true, nullptr, 1, 1, 0,0,0,0,0,0};
            gemm128x128(g);
        }

        // V^T, suffix scan
        transpose(qkv + 2*H_*HS_, vT, BT_, D_, QKVW_, BT_, 1, 1, 0, 0, 0, 0, 0);
        suffixv_kernel<<<192, 256>>>(vT, sufv);

        // fused attention (+ suffix-V correction in epilogue)
        attn_kernel<<<dim3(B_*H_, T_/128), 256, AT_SMEM>>>(qkv, vT, sufv, av);

        // x += av @ Wo[l]
        {
            GemmArgs g{av, woT + (long long)l*D_*H_*HS_, x, nullptr,
                       BT_, D_, H_*HS_, H_*HS_, H_*HS_, D_,
                       true, false, false, nullptr, 1, 1, 0,0,0,0,0,0};
            gemm128x128(g);
        }

        ln_kernel<<<BT_/8, 256>>>(x, ln2_g + l*D_, ln2_b + l*D_, h);

        // ffn
        {
            GemmArgs g{h, w1T + (long long)l*DFF_*D_, ffn, b1 + l*DFF_,
                       BT_, DFF_, D_, D_, D_, DFF_,
                       false, true, true, nullptr, 1, 1, 0,0,0,0,0,0};
            gemm128x128(g);
        }
        {
            GemmArgs g{ffn, w2T + (long long)l*D_*DFF_, x, b2 + l*D_,
                       BT_, D_, DFF_, DFF_, DFF_, D_,
                       true, false, false, nullptr, 1, 1, 0,0,0,0,0,0};
            gemm128x128(g);
        }
    }

    ln_kernel<<<BT_/8, 256>>>(x, lnf_g, lnf_b, h);

    // LM head with fused LSE partials (250 chunks)
    {
        GemmArgs g{h, wlmT, logits, blm,
                   BT_, V_, D_, D_, D_, V_,
                   false, false, false, lsp, 1, 1, 0,0,0,0,0,0};
        gemm128x128(g);
    }

    lossrow2_kernel<<<BT_/8, 256>>>(lsp, NCH_, logits, targets, rl);
    if (out_has_logits && (long long)out_size > NLOGITS) {
        lossreduce_kernel<<<1, 256>>>(rl, out + NLOGITS);
    } else if (!out_has_logits && out_size >= 1) {
        lossreduce_kernel<<<1, 256>>>(rl, out);
    }
}

// round 17
// speedup vs baseline: 1.5664x; 1.0118x over previous
#include <cuda_runtime.h>
#include <cuda_bf16.h>
#include <math.h>
#include <stdint.h>

// Problem dims
#define B_  4
#define T_  1024
#define V_  32000
#define D_  384
#define H_  6
#define HS_ 64
#define L_  6
#define DFF_ 1536
#define BT_ (B_*T_)
#define QKVW_ (3*H_*HS_)   // 1152
#define NCH_ (V_/128)      // lsepart capacity
#define EPS_ 1e-5f
#define SCALE_ 0.125f

// ---------------- static scratch ----------------
__device__ float g_x[BT_*D_];
__device__ float g_h[BT_*D_];
__device__ float g_qkv[(size_t)BT_*QKVW_];
__device__ float g_wpack[(size_t)L_*QKVW_*D_];
__device__ float g_woT[(size_t)L_*D_*(H_*HS_)];
__device__ float g_w1T[(size_t)L_*DFF_*D_];
__device__ float g_w2T[(size_t)L_*D_*DFF_];
__device__ float g_wlmT[(size_t)V_*D_];
__device__ float g_vT[(size_t)D_*BT_];
__device__ float g_av[BT_*D_];
__device__ float g_ffn[BT_*DFF_];
__device__ float g_sufv[(size_t)B_*H_*T_*HS_];
__device__ float2 g_lsepart[(size_t)BT_*NCH_];
__device__ float g_rowloss[BT_];
__device__ float g_logits[(size_t)BT_*V_];

// ---------------- tf32 helper ----------------
__device__ __forceinline__ float tf32r(float x)
{
    asm("cvt.rna.tf32.f32 %0, %0;" : "+f"(x));
    return x;
}
#define FU(x) __float_as_uint(x)

// ---------------- embed ----------------
__global__ void embed_kernel(const int* __restrict__ tok,
                             const float* __restrict__ tt,
                             const float* __restrict__ pt,
                             float* __restrict__ x)
{
    int idx = blockIdx.x * blockDim.x + threadIdx.x;
    if (idx >= BT_*D_) return;
    int bt = idx / D_;
    int d  = idx - bt * D_;
    int t  = bt % T_;
    x[idx] = tt[(size_t)tok[bt] * D_ + d] + pt[t * D_ + d];
}

// ---------------- tiled transpose ----------------
__global__ void transpose_kernel(const float* __restrict__ in,
                                 float* __restrict__ out,
                                 int ldi, int ldo, int zdiv, int roundout,
                                 long long sId, long long sIm,
                                 long long sOd, long long sOm)
{
    __shared__ float tile[32][33];
    int z  = blockIdx.z;
    int zq = z / zdiv;
    int zr = z - zq * zdiv;
    in  += zq * sId + (long long)zr * sIm;
    out += zq * sOd + (long long)zr * sOm;

    int r0 = blockIdx.y * 32;
    int c0 = blockIdx.x * 32;
    int tx = threadIdx.x, ty = threadIdx.y;
    #pragma unroll
    for (int j = 0; j < 4; j++)
        tile[ty + 8*j][tx] = in[(size_t)(r0 + ty + 8*j) * ldi + c0 + tx];
    __syncthreads();
    #pragma unroll
    for (int j = 0; j < 4; j++) {
        float v = tile[tx][ty + 8*j];
        if (roundout) v = tf32r(v);
        out[(size_t)(c0 + ty + 8*j) * ldo + r0 + tx] = v;
    }
}

// ---------------- layernorm: warp per row ----------------
__global__ void ln_kernel(const float* __restrict__ x,
                          const float* __restrict__ g,
                          const float* __restrict__ b,
                          float* __restrict__ y)
{
    int warp = threadIdx.x >> 5;
    int lane = threadIdx.x & 31;
    size_t row = (size_t)blockIdx.x * 8 + warp;
    const float4* xr = (const float4*)(x + row * D_);
    const float4* g4 = (const float4*)g;
    const float4* b4 = (const float4*)b;
    float4* yr = (float4*)(y + row * D_);

    float4 v[3];
    float s = 0.f, q = 0.f;
    #pragma unroll
    for (int i = 0; i < 3; i++) {
        v[i] = xr[lane + i*32];
        s += v[i].x + v[i].y + v[i].z + v[i].w;
        q += v[i].x*v[i].x + v[i].y*v[i].y + v[i].z*v[i].z + v[i].w*v[i].w;
    }
    #pragma unroll
    for (int off = 16; off > 0; off >>= 1) {
        s += __shfl_xor_sync(0xffffffffu, s, off);
        q += __shfl_xor_sync(0xffffffffu, q, off);
    }
    float mean = s * (1.0f / D_);
    float var  = q * (1.0f / D_) - mean * mean;
    float inv  = rsqrtf(var + EPS_);
    #pragma unroll
    for (int i = 0; i < 3; i++) {
        float4 gg = g4[lane + i*32];
        float4 bb = b4[lane + i*32];
        float4 o;
        o.x = tf32r((v[i].x - mean) * inv * gg.x + bb.x);
        o.y = tf32r((v[i].y - mean) * inv * gg.y + bb.y);
        o.z = tf32r((v[i].z - mean) * inv * gg.z + bb.z);
        o.w = tf32r((v[i].w - mean) * inv * gg.w + bb.w);
        yr[lane + i*32] = o;
    }
}

__device__ __forceinline__ void mma_tf32(float c[4],
    uint32_t a0, uint32_t a1, uint32_t a2, uint32_t a3,
    uint32_t b0, uint32_t b1)
{
    asm volatile(
        "mma.sync.aligned.m16n8k8.row.col.f32.tf32.tf32.f32 "
        "{%0,%1,%2,%3}, {%4,%5,%6,%7}, {%8,%9}, {%0,%1,%2,%3};"
        : "+f"(c[0]), "+f"(c[1]), "+f"(c[2]), "+f"(c[3])
        : "r"(a0), "r"(a1), "r"(a2), "r"(a3), "r"(b0), "r"(b1));
}

// ---------------- NT tensor-core GEMM, cp.async 4-stage (dynamic smem, occ 2) ----
// NTH = thread count = 32 * (BM/WM) * (BN/WN)
template<int BM, int BN, int WM, int WN, int NTH>
__global__ void __launch_bounds__(NTH, 2)
ntgemm_kernel(const float* __restrict__ A,
              const float* __restrict__ B,
              float* __restrict__ C,
              const float* __restrict__ bias,
              int K, int lda, int ldb, int ldc,
              int accumulate, int relu, int roundout,
              float2* lsepart, int zdiv,
              long long sAd, long long sAm,
              long long sBd, long long sBm,
              long long sCd, long long sCm)
{
    constexpr int BK = 16;
    constexpr int NSTAGE = 4;
    constexpr int MT = WM / 16;
    constexpr int NT = WN / 8;
    constexpr int WARPS_N = BN / WN;
    static_assert((BM/WM) * (BN/WN) * 32 == NTH, "thread count");
    constexpr int RPP = NTH / 4;        // staging rows per pass
    constexpr int APT = BM / RPP;
    constexpr int BPT = BN / RPP;

    extern __shared__ float dynsm[];
    float (*As)[BM][BK] = (float(*)[BM][BK])dynsm;
    float (*Bs)[BN][BK] = (float(*)[BN][BK])(dynsm + NSTAGE*BM*BK);

    const int row0 = blockIdx.y * BM;
    const int col0 = blockIdx.x * BN;

    int z  = blockIdx.z;
    int zq = z / zdiv;
    int zr = z - zq * zdiv;
    A += zq * sAd + (long long)zr * sAm;
    B += zq * sBd + (long long)zr * sBm;
    C += zq * sCd + (long long)zr * sCm;

    const int tid  = threadIdx.x;
    const int lane = tid & 31;
    const int wid  = tid >> 5;
    const int wm   = wid / WARPS_N;
    const int wn   = wid % WARPS_N;
    const int gid  = lane >> 2;
    const int tig4 = (lane & 3) * 4;

    float acc[MT][NT][4] = {};

    const int s_row = tid >> 2;
    const int s_kq  = (tid & 3) * 4;

    auto ISSUE = [&](int stage, int k0) {
        if (k0 < K) {
            #pragma unroll
            for (int i = 0; i < APT; i++) {
                uint32_t dst = (uint32_t)__cvta_generic_to_shared(&As[stage][s_row + i*RPP][s_kq]);
                const float* src = A + (size_t)(row0 + s_row + i*RPP) * lda + k0 + s_kq;
                asm volatile("cp.async.cg.shared.global [%0], [%1], 16;\n" :: "r"(dst), "l"(src));
            }
            #pragma unroll
            for (int i = 0; i < BPT; i++) {
                uint32_t dst = (uint32_t)__cvta_generic_to_shared(&Bs[stage][s_row + i*RPP][s_kq]);
                const float* src = B + (size_t)(col0 + s_row + i*RPP) * ldb + k0 + s_kq;
                asm volatile("cp.async.cg.shared.global [%0], [%1], 16;\n" :: "r"(dst), "l"(src));
            }
        }
        asm volatile("cp.async.commit_group;\n");
    };

    auto COMPUTE = [&](int buf) {
        float4 bq[NT];
        #pragma unroll
        for (int nt = 0; nt < NT; nt++)
            bq[nt] = *(const float4*)&Bs[buf][wn*WN + nt*8 + gid][tig4];
        #pragma unroll
        for (int mt = 0; mt < MT; mt++) {
            int m0 = wm*WM + mt*16 + gid;
            float4 a0 = *(const float4*)&As[buf][m0    ][tig4];
            float4 a1 = *(const float4*)&As[buf][m0 + 8][tig4];
            #pragma unroll
            for (int nt = 0; nt < NT; nt++) {
                mma_tf32(acc[mt][nt], FU(a0.x), FU(a1.x), FU(a0.y), FU(a1.y),
                         FU(bq[nt].x), FU(bq[nt].y));
                mma_tf32(acc[mt][nt], FU(a0.z), FU(a1.z), FU(a0.w), FU(a1.w),
                         FU(bq[nt].z), FU(bq[nt].w));
            }
        }
    };

    ISSUE(0, 0);
    ISSUE(1, BK);
    ISSUE(2, 2*BK);

    const int niter = K / BK;
    for (int it = 0; it < niter; it++) {
        asm volatile("cp.async.wait_group 2;\n");
        __syncthreads();
        ISSUE((it + NSTAGE - 1) % NSTAGE, (it + NSTAGE - 1) * BK);
        COMPUTE(it % NSTAGE);
    }

    if (lsepart) {
        asm volatile("cp.async.wait_group 0;\n");
        __syncthreads();
        float2* lse_s = (float2*)dynsm;
        #pragma unroll
        for (int mt = 0; mt < MT; mt++) {
            float va[2][NT*2];
            #pragma unroll
            for (int nt = 0; nt < NT; nt++) {
                int r = row0 + wm*WM + mt*16 + gid;
                int c = col0 + wn*WN + nt*8 + (lane & 3)*2;
                float2 v0 = make_float2(acc[mt][nt][0], acc[mt][nt][1]);
                float2 v1 = make_float2(acc[mt][nt][2], acc[mt][nt][3]);
                if (bias) {
                    float2 bb = *(const float2*)(bias + c);
                    v0.x += bb.x; v0.y += bb.y;
                    v1.x += bb.x; v1.y += bb.y;
                }
                *(float2*)(C + (size_t)r * ldc + c)     = v0;
                *(float2*)(C + (size_t)(r+8) * ldc + c) = v1;
                va[0][nt*2] = v0.x; va[0][nt*2+1] = v0.y;
                va[1][nt*2] = v1.x; va[1][nt*2+1] = v1.y;
            }
            #pragma unroll
            for (int hf = 0; hf < 2; hf++) {
                float mx = va[hf][0];
                #pragma unroll
                for (int j = 1; j < NT*2; j++) mx = fmaxf(mx, va[hf][j]);
                float sm = 0.f;
                #pragma unroll
                for (int j = 0; j < NT*2; j++) sm += __expf(va[hf][j] - mx);
                #pragma unroll
                for (int off = 1; off <= 2; off <<= 1) {
                    float mo = __shfl_xor_sync(0xffffffffu, mx, off);
                    float so = __shfl_xor_sync(0xffffffffu, sm, off);
                    float M = fmaxf(mx, mo);
                    sm = sm*__expf(mx - M) + so*__expf(mo - M);
                    mx = M;
                }
                if ((lane & 3) == 0) {
                    int rl = wm*WM + mt*16 + gid + hf*8;
                    lse_s[rl*WARPS_N + wn] = make_float2(mx, sm);
                }
            }
        }
        __syncthreads();
        for (int r = tid; r < BM; r += NTH) {
            float2 a = lse_s[r*WARPS_N];
            #pragma unroll
            for (int w = 1; w < WARPS_N; w++) {
                float2 b = lse_s[r*WARPS_N + w];
                float M = fmaxf(a.x, b.x);
                a = make_float2(M, a.y*__expf(a.x - M) + b.y*__expf(b.x - M));
            }
            lsepart[(size_t)(row0 + r) * gridDim.x + blockIdx.x] = a;
        }
        return;
    }

    #pragma unroll
    for (int mt = 0; mt < MT; mt++) {
        #pragma unroll
        for (int nt = 0; nt < NT; nt++) {
            int r = row0 + wm*WM + mt*16 + gid;
            int c = col0 + wn*WN + nt*8 + (lane & 3)*2;
            float2 v0 = make_float2(acc[mt][nt][0], acc[mt][nt][1]);
            float2 v1 = make_float2(acc[mt][nt][2], acc[mt][nt][3]);
            if (bias) {
                float2 bb = *(const float2*)(bias + c);
                v0.x += bb.x; v0.y += bb.y;
                v1.x += bb.x; v1.y += bb.y;
            }
            float* p0 = C + (size_t)r * ldc + c;
            float* p1 = C + (size_t)(r+8) * ldc + c;
            if (accumulate) {
                float2 c0 = *(const float2*)p0;
                float2 c1 = *(const float2*)p1;
                v0.x += c0.x; v0.y += c0.y;
                v1.x += c1.x; v1.y += c1.y;
            }
            if (relu) {
                v0.x = fmaxf(v0.x, 0.f); v0.y = fmaxf(v0.y, 0.f);
                v1.x = fmaxf(v1.x, 0.f); v1.y = fmaxf(v1.y, 0.f);
            }
            if (roundout) {
                v0.x = tf32r(v0.x); v0.y = tf32r(v0.y);
                v1.x = tf32r(v1.x); v1.y = tf32r(v1.y);
            }
            *(float2*)p0 = v0;
            *(float2*)p1 = v1;
        }
    }
}
#define GEMM_DSMEM (4*(128+128)*16*4)

// ---------------- fused attention, K-prefetched ----------------
#define AT_SMEM ((128*64 + 64*64 + 64*64 + 128*64 + 256 + 256)*4)

__global__ void __launch_bounds__(256, 2)
attn_kernel(const float* __restrict__ qkv,
            const float* __restrict__ vT,
            const float* __restrict__ sufv,
            float* __restrict__ av)
{
    extern __shared__ float sm[];
    float* Qs   = sm;
    float* Ks   = Qs + 128*64;
    float* Vs   = Ks + 64*64;
    float* Ps   = Vs + 64*64;
    float* rmax = Ps + 128*64;
    float* rsum = rmax + 256;

    const int bh = blockIdx.x;
    const int b = bh / H_, h = bh - b*H_;
    const int row0 = (gridDim.y - 1 - blockIdx.y) * 128;

    const int tid  = threadIdx.x;
    const int lane = tid & 31;
    const int wid  = tid >> 5;
    const int wm   = wid >> 1;
    const int wn   = wid & 1;
    const int gid  = lane >> 2;
    const int tig  = lane & 3;

    const float* kbase0 = qkv + (size_t)(b*T_) * QKVW_ + H_*HS_ + h*HS_;
    const float* vbase0 = vT + (size_t)(h*HS_) * BT_ + b*T_;

    auto ISSUE_K = [&](int j) {
        const float* kb = kbase0 + (size_t)(j*64) * QKVW_;
        #pragma unroll
        for (int i = 0; i < 4; i++) {
            int idx = tid + i*256;
            int r = idx >> 4, c = idx & 15;
            int cc = (c + ((r & 3) << 2)) & 15;
            uint32_t dk = (uint32_t)__cvta_generic_to_shared(Ks + r*64 + cc*4);
            asm volatile("cp.async.cg.shared.global [%0], [%1], 16;\n"
                         :: "r"(dk), "l"(kb + (size_t)r * QKVW_ + c*4));
        }
        asm volatile("cp.async.commit_group;\n");
    };
    auto ISSUE_V = [&](int j) {
        const float* vb = vbase0 + j*64;
        #pragma unroll
        for (int i = 0; i < 4; i++) {
            int idx = tid + i*256;
            int r = idx >> 4, c = idx & 15;
            int cc = (c + ((r & 3) << 2)) & 15;
            uint32_t dv = (uint32_t)__cvta_generic_to_shared(Vs + r*64 + cc*4);
            asm volatile("cp.async.cg.shared.global [%0], [%1], 16;\n"
                         :: "r"(dv), "l"(vb + (size_t)r * BT_ + c*4));
        }
        asm volatile("cp.async.commit_group;\n");
    };

    {
        const float* qbase = qkv + (size_t)(b*T_ + row0) * QKVW_ + h*HS_;
        #pragma unroll
        for (int i = 0; i < 8; i++) {
            int idx = tid + i*256;
            int r = idx >> 4, c = idx & 15;
            int cc = (c + ((r & 3) << 2)) & 15;
            uint32_t dst = (uint32_t)__cvta_generic_to_shared(Qs + r*64 + cc*4);
            const float* src = qbase + (size_t)r * QKVW_ + c*4;
            asm volatile("cp.async.cg.shared.global [%0], [%1], 16;\n" :: "r"(dst), "l"(src));
        }
        asm volatile("cp.async.commit_group;\n");
    }
    ISSUE_K(0);

    float m_run[2][2], s_run[2][2];
    float acc_o[2][4][4] = {};
    #pragma unroll
    for (int mt = 0; mt < 2; mt++)
        #pragma unroll
        for (int k = 0; k < 2; k++) { m_run[mt][k] = -1e30f; s_run[mt][k] = 0.f; }

    const int jmax = row0/64 + 2;

    for (int j = 0; j < jmax; j++) {
        __syncthreads();
        ISSUE_V(j);
        asm volatile("cp.async.wait_group 0;\n");
        __syncthreads();

        float acc_s[2][4][4] = {};
        #pragma unroll
        for (int ks = 0; ks < 4; ks++) {
            int fidx = ((ks*16 + tig*4) + ((gid & 3) << 4)) & 63;
            float4 bq[4];
            #pragma unroll
            for (int nt = 0; nt < 4; nt++) {
                int n0 = wn*32 + nt*8 + gid;
                bq[nt] = *(const float4*)&Ks[n0*64 + fidx];
            }
            #pragma unroll
            for (int mt = 0; mt < 2; mt++) {
                int m0 = wm*32 + mt*16 + gid;
                float4 a0 = *(const float4*)&Qs[m0*64 + fidx];
                float4 a1 = *(const float4*)&Qs[(m0+8)*64 + fidx];
                #pragma unroll
                for (int nt = 0; nt < 4; nt++) {
                    mma_tf32(acc_s[mt][nt], FU(a0.x), FU(a1.x), FU(a0.y), FU(a1.y),
                             FU(bq[nt].x), FU(bq[nt].y));
                    mma_tf32(acc_s[mt][nt], FU(a0.z), FU(a1.z), FU(a0.w), FU(a1.w),
                             FU(bq[nt].z), FU(bq[nt].w));
                }
            }
        }

        float tmax[2][2];
        #pragma unroll
        for (int mt = 0; mt < 2; mt++) {
            int t0 = row0 + wm*32 + mt*16 + gid;
            int t1 = t0 + 8;
            tmax[mt][0] = -1e30f; tmax[mt][1] = -1e30f;
            #pragma unroll
            for (int nt = 0; nt < 4; nt++) {
                int c0 = j*64 + wn*32 + nt*8 + tig*2;
                float* a = acc_s[mt][nt];
                a[0] = (c0   <= t0) ? a[0]*SCALE_ : -1e30f;
                a[1] = (c0+1 <= t0) ? a[1]*SCALE_ : -1e30f;
                a[2] = (c0   <= t1) ? a[2]*SCALE_ : -1e30f;
                a[3] = (c0+1 <= t1) ? a[3]*SCALE_ : -1e30f;
                tmax[mt][0] = fmaxf(tmax[mt][0], fmaxf(a[0], a[1]));
                tmax[mt][1] = fmaxf(tmax[mt][1], fmaxf(a[2], a[3]));
            }
            #pragma unroll
            for (int off = 1; off <= 2; off <<= 1) {
                tmax[mt][0] = fmaxf(tmax[mt][0], __shfl_xor_sync(0xffffffffu, tmax[mt][0], off));
                tmax[mt][1] = fmaxf(tmax[mt][1], __shfl_xor_sync(0xffffffffu, tmax[mt][1], off));
            }
            if (tig == 0) {
                int rl = wm*32 + mt*16 + gid;
                rmax[rl*2 + wn]     = tmax[mt][0];
                rmax[(rl+8)*2 + wn] = tmax[mt][1];
            }
        }
        __syncthreads();

        if (j + 1 < jmax) ISSUE_K(j + 1);

        float alpha[2][2], psum[2][2];
        #pragma unroll
        for (int mt = 0; mt < 2; mt++) {
            #pragma unroll
            for (int k = 0; k < 2; k++) {
                int rl = wm*32 + mt*16 + gid + k*8;
                float tm = fmaxf(rmax[rl*2], rmax[rl*2+1]);
                float mn = fmaxf(m_run[mt][k], tm);
                alpha[mt][k] = __expf(m_run[mt][k] - mn);
                m_run[mt][k] = mn;
                psum[mt][k] = 0.f;
            }
        }
        #pragma unroll
        for (int mt = 0; mt < 2; mt++) {
            int r0l = wm*32 + mt*16 + gid;
            int rot = (r0l & 3) << 4;
            #pragma unroll
            for (int nt = 0; nt < 4; nt++) {
                float* a = acc_s[mt][nt];
                float p0 = __expf(a[0] - m_run[mt][0]);
                float p1 = __expf(a[1] - m_run[mt][0]);
                float p2 = __expf(a[2] - m_run[mt][1]);
                float p3 = __expf(a[3] - m_run[mt][1]);
                psum[mt][0] += p0 + p1;
                psum[mt][1] += p2 + p3;
                int c = wn*32 + nt*8 + tig*2;
                int f = (c + rot) & 63;
                *(float2*)&Ps[r0l*64 + f]     = make_float2(tf32r(p0), tf32r(p1));
                *(float2*)&Ps[(r0l+8)*64 + f] = make_float2(tf32r(p2), tf32r(p3));
                float* o = acc_o[mt][nt];
                o[0] *= alpha[mt][0]; o[1] *= alpha[mt][0];
                o[2] *= alpha[mt][1]; o[3] *= alpha[mt][1];
            }
            #pragma unroll
            for (int off = 1; off <= 2; off <<= 1) {
                psum[mt][0] += __shfl_xor_sync(0xffffffffu, psum[mt][0], off);
                psum[mt][1] += __shfl_xor_sync(0xffffffffu, psum[mt][1], off);
            }
            if (tig == 0) {
                rsum[r0l*2 + wn]     = psum[mt][0];
                rsum[(r0l+8)*2 + wn] = psum[mt][1];
            }
        }
        __syncthreads();
        #pragma unroll
        for (int mt = 0; mt < 2; mt++) {
            #pragma unroll
            for (int k = 0; k < 2; k++) {
                int rl = wm*32 + mt*16 + gid + k*8;
                float ts = rsum[rl*2] + rsum[rl*2+1];
                s_run[mt][k] = s_run[mt][k]*alpha[mt][k] + ts;
            }
        }

        #pragma unroll
        for (int ks = 0; ks < 4; ks++) {
            int fidx = ((ks*16 + tig*4) + ((gid & 3) << 4)) & 63;
            float4 bq[4];
            #pragma unroll
            for (int nt = 0; nt < 4; nt++) {
                int e0 = wn*32 + nt*8 + gid;
                bq[nt] = *(const float4*)&Vs[e0*64 + fidx];
            }
            #pragma unroll
            for (int mt = 0; mt < 2; mt++) {
                int m0 = wm*32 + mt*16 + gid;
                float4 a0 = *(const float4*)&Ps[m0*64 + fidx];
                float4 a1 = *(const float4*)&Ps[(m0+8)*64 + fidx];
                #pragma unroll
                for (int nt = 0; nt < 4; nt++) {
                    mma_tf32(acc_o[mt][nt], FU(a0.x), FU(a1.x), FU(a0.y), FU(a1.y),
                             FU(bq[nt].x), FU(bq[nt].y));
                    mma_tf32(acc_o[mt][nt], FU(a0.z), FU(a1.z), FU(a0.w), FU(a1.w),
                             FU(bq[nt].z), FU(bq[nt].w));
                }
            }
        }
    }

    float oscale[2][2], wmr[2][2];
    #pragma unroll
    for (int mt = 0; mt < 2; mt++) {
        #pragma unroll
        for (int k = 0; k < 2; k++) {
            int t = row0 + wm*32 + mt*16 + gid + k*8;
            float mr = m_run[mt][k], sr = s_run[mt][k];
            int count = T_ - 1 - t;
            float mf = (count > 0) ? fmaxf(mr, 0.f) : mr;
            float emm = __expf(mr - mf);
            float denom = sr * emm + (float)count * __expf(-mf);
            oscale[mt][k] = emm / denom;
            wmr[mt][k]    = __expf(-mf) / denom;
        }
    }
    #pragma unroll
    for (int mt = 0; mt < 2; mt++) {
        int r = row0 + wm*32 + mt*16 + gid;
        const float* suf0 = sufv + ((size_t)bh*T_ + r) * HS_;
        const float* suf1 = suf0 + (size_t)8 * HS_;
        #pragma unroll
        for (int nt = 0; nt < 4; nt++) {
            int c = wn*32 + nt*8 + tig*2;
            float* dst = av + (size_t)(b*T_ + r)*D_ + h*HS_ + c;
            float* o = acc_o[mt][nt];
            float2 sv0 = *(const float2*)(suf0 + c);
            float2 sv1 = *(const float2*)(suf1 + c);
            *(float2*)dst = make_float2(
                tf32r(fmaf(wmr[mt][0], sv0.x, o[0]*oscale[mt][0])),
                tf32r(fmaf(wmr[mt][0], sv0.y, o[1]*oscale[mt][0])));
            *(float2*)(dst + 8*D_) = make_float2(
                tf32r(fmaf(wmr[mt][1], sv1.x, o[2]*oscale[mt][1])),
                tf32r(fmaf(wmr[mt][1], sv1.y, o[3]*oscale[mt][1])));
        }
    }
}

// ---------------- parallel V suffix scan ----------------
__global__ void suffixv_kernel(const float* __restrict__ vT, float* __restrict__ suf)
{
    int gw   = blockIdx.x * 8 + (threadIdx.x >> 5);
    int lane = threadIdx.x & 31;
    int e  = gw >> 2;
    int b  = gw & 3;
    int bh = b * H_ + (e >> 6);
    int ep = e & 63;
    const float* src = vT + (size_t)e * BT_ + b * T_;
    float* dst = suf + (size_t)bh * T_ * HS_ + ep;

    float carry = 0.f;
    for (int j = 31; j >= 0; j--) {
        int t = j*32 + lane;
        float v = src[t];
        float s = v;
        #pragma unroll
        for (int off = 1; off < 32; off <<= 1) {
            float o = __shfl_down_sync(0xffffffffu, s, off);
            if (lane + off < 32) s += o;
        }
        dst[(size_t)t * HS_] = s - v + carry;
        carry += __shfl_sync(0xffffffffu, s, 0);
    }
}

// ---------------- loss from LM-head partials (8 rows / block) ----------------
__global__ void lossrow2_kernel(const float2* __restrict__ part, int nch,
                                const float* __restrict__ logits,
                                const int* __restrict__ tgt,
                                float* __restrict__ rowloss)
{
    int row  = blockIdx.x * 8 + (threadIdx.x >> 5);
    int lane = threadIdx.x & 31;
    float m = -1e30f, s = 0.f;
    for (int i = lane; i < nch; i += 32) {
        float2 p = part[(size_t)row*nch + i];
        float M = fmaxf(m, p.x);
        s = s*__expf(m - M) + p.y*__expf(p.x - M);
        m = M;
    }
    #pragma unroll
    for (int off = 16; off > 0; off >>= 1) {
        float mo = __shfl_xor_sync(0xffffffffu, m, off);
        float so = __shfl_xor_sync(0xffffffffu, s, off);
        float M = fmaxf(m, mo);
        s = s*__expf(m - M) + so*__expf(mo - M);
        m = M;
    }
    if (lane == 0)
        rowloss[row] = m + logf(s) - logits[(size_t)row*V_ + tgt[row]];
}

__global__ void lossreduce_kernel(const float* __restrict__ rowloss,
                                  float* __restrict__ out)
{
    __shared__ float red[256];
    int tid = threadIdx.x;
    float s = 0.f;
    for (int i = tid; i < BT_; i += 256) s += rowloss[i];
    red[tid] = s; __syncthreads();
    for (int off = 128; off > 0; off >>= 1) {
        if (tid < off) red[tid] += red[tid+off];
        __syncthreads();
    }
    if (tid == 0) out[0] = red[0] / (float)BT_;
}

// ---------------- host ----------------
static float* sym(const void* s)
{
    void* p = nullptr;
    cudaGetSymbolAddress(&p, s);
    return (float*)p;
}

struct GemmArgs {
    const float *A, *B; float* C; const float* bias;
    int M, N, K, lda, ldb, ldc;
    bool acc, relu, round;
    float2* lsepart;
    int Z, zdiv;
    long long sAd, sAm, sBd, sBm, sCd, sCm;
};

// standard 8-warp config (proven)
static void gemm128x128(const GemmArgs& g)
{
    dim3 grid(g.N / 128, g.M / 128, g.Z);
    ntgemm_kernel<128,128,64,32,256><<<grid, 256, GEMM_DSMEM>>>(
        g.A, g.B, g.C, g.bias, g.K, g.lda, g.ldb, g.ldc,
        g.acc, g.relu, g.round, g.lsepart, g.zdiv,
        g.sAd, g.sAm, g.sBd, g.sBm, g.sCd, g.sCm);
}

// 4-warp 64x64-warp-tile config (higher LDS reuse) — LM head
static void gemm128x128w(const GemmArgs& g)
{
    dim3 grid(g.N / 128, g.M / 128, g.Z);
    ntgemm_kernel<128,128,64,64,128><<<grid, 128, GEMM_DSMEM>>>(
        g.A, g.B, g.C, g.bias, g.K, g.lda, g.ldb, g.ldc,
        g.acc, g.relu, g.round, g.lsepart, g.zdiv,
        g.sAd, g.sAm, g.sBd, g.sBm, g.sCd, g.sCm);
}

static void transpose(const float* in, float* out, int R, int C,
                      int ldi, int ldo, int Z, int zdiv, int roundout,
                      long long sId, long long sIm,
                      long long sOd, long long sOm)
{
    dim3 grid(C / 32, R / 32, Z);
    transpose_kernel<<<grid, dim3(32, 8)>>>(in, out, ldi, ldo, zdiv, roundout,
                                            sId, sIm, sOd, sOm);
}

extern "C" void kernel_launch(void* const* d_in, const int* in_sizes, int n_in,
                              void* d_out, int out_size)
{
    const int*   token_ids = (const int*)d_in[0];
    const int*   targets   = (const int*)d_in[1];
    const float* tok_table = (const float*)d_in[2];
    const float* pos_table = (const float*)d_in[3];
    const float* ln1_g = (const float*)d_in[4];
    const float* ln1_b = (const float*)d_in[5];
    const float* Wq = (const float*)d_in[6];
    const float* Wk = (const float*)d_in[7];
    const float* Wv = (const float*)d_in[8];
    const float* Wo = (const float*)d_in[9];
    const float* ln2_g = (const float*)d_in[10];
    const float* ln2_b = (const float*)d_in[11];
    const float* W1 = (const float*)d_in[12];
    const float* b1 = (const float*)d_in[13];
    const float* W2 = (const float*)d_in[14];
    const float* b2 = (const float*)d_in[15];
    const float* lnf_g = (const float*)d_in[16];
    const float* lnf_b = (const float*)d_in[17];
    const float* Wlm = (const float*)d_in[18];
    const float* blm = (const float*)d_in[19];

    cudaFuncSetAttribute(attn_kernel,
                         cudaFuncAttributeMaxDynamicSharedMemorySize, AT_SMEM);
    cudaFuncSetAttribute(ntgemm_kernel<128,128,64,32,256>,
                         cudaFuncAttributeMaxDynamicSharedMemorySize, GEMM_DSMEM);
    cudaFuncSetAttribute(ntgemm_kernel<128,128,64,64,128>,
                         cudaFuncAttributeMaxDynamicSharedMemorySize, GEMM_DSMEM);

    float* x    = sym(g_x);
    float* h    = sym(g_h);
    float* qkv  = sym(g_qkv);
    float* wp   = sym(g_wpack);
    float* woT  = sym(g_woT);
    float* w1T  = sym(g_w1T);
    float* w2T  = sym(g_w2T);
    float* wlmT = sym(g_wlmT);
    float* vT   = sym(g_vT);
    float* av   = sym(g_av);
    float* ffn  = sym(g_ffn);
    float* sufv = sym(g_sufv);
    float2* lsp = (float2*)sym(g_lsepart);
    float* rl   = sym(g_rowloss);

    const long long NLOGITS = (long long)BT_ * V_;
    float* out = (float*)d_out;
    bool out_has_logits = ((long long)out_size >= NLOGITS);
    float* logits = out_has_logits ? out : sym(g_logits);

    // ---- embed + weight packs ----
    embed_kernel<<<(BT_*D_ + 255)/256, 256>>>(token_ids, tok_table, pos_table, x);
    for (int grp = 0; grp < 3; grp++) {
        const float* W = (grp == 0) ? Wq : (grp == 1) ? Wk : Wv;
        transpose(W, wp + (long long)grp*H_*HS_*D_, D_, HS_, HS_, D_,
                  L_*H_, H_, 1,
                  (long long)H_*D_*HS_, (long long)D_*HS_,
                  (long long)QKVW_*D_, (long long)HS_*D_);
    }
    transpose(Wo, woT, H_*HS_, D_, D_, H_*HS_, L_, 1, 1,
              (long long)H_*HS_*D_, 0, (long long)D_*H_*HS_, 0);
    transpose(W1, w1T, D_, DFF_, DFF_, D_, L_, 1, 1,
              (long long)D_*DFF_, 0, (long long)DFF_*D_, 0);
    transpose(W2, w2T, DFF_, D_, D_, DFF_, L_, 1, 1,
              (long long)DFF_*D_, 0, (long long)D_*DFF_, 0);
    transpose(Wlm, wlmT, D_, V_, V_, D_, 1, 1, 1, 0, 0, 0, 0);

    for (int l = 0; l < L_; l++) {
        ln_kernel<<<BT_/8, 256>>>(x, ln1_g + l*D_, ln1_b + l*D_, h);

        // fused QKV (rounded)
        {
            GemmArgs g{h, wp + (long long)l*QKVW_*D_, qkv, nullptr,
                       BT_, QKVW_, D_, D_, D_, QKVW_,
                       false, false, true, nullptr, 1, 1, 0,0,0,0,0,0};
            gemm128x128(g);
        }

        // V^T, suffix scan
        transpose(qkv + 2*H_*HS_, vT, BT_, D_, QKVW_, BT_, 1, 1, 0, 0, 0, 0, 0);
        suffixv_kernel<<<192, 256>>>(vT, sufv);

        // fused attention (+ suffix-V correction in epilogue)
        attn_kernel<<<dim3(B_*H_, T_/128), 256, AT_SMEM>>>(qkv, vT, sufv, av);

        // x += av @ Wo[l]
        {
            GemmArgs g{av, woT + (long long)l*D_*H_*HS_, x, nullptr,
                       BT_, D_, H_*HS_, H_*HS_, H_*HS_, D_,
                       true, false, false, nullptr, 1, 1, 0,0,0,0,0,0};
            gemm128x128(g);
        }

        ln_kernel<<<BT_/8, 256>>>(x, ln2_g + l*D_, ln2_b + l*D_, h);

        // ffn
        {
            GemmArgs g{h, w1T + (long long)l*DFF_*D_, ffn, b1 + l*DFF_,
                       BT_, DFF_, D_, D_, D_, DFF_,
                       false, true, true, nullptr, 1, 1, 0,0,0,0,0,0};
            gemm128x128(g);
        }
        {
            GemmArgs g{ffn, w2T + (long long)l*D_*DFF_, x, b2 + l*D_,
                       BT_, D_, DFF_, DFF_, DFF_, D_,
                       true, false, false, nullptr, 1, 1, 0,0,0,0,0,0};
            gemm128x128(g);
        }
    }

    ln_kernel<<<BT_/8, 256>>>(x, lnf_g, lnf_b, h);

    // LM head on the 64x64-warp-tile config (wave-rich: 8000 CTAs)
    {
        GemmArgs g{h, wlmT, logits, blm,
                   BT_, V_, D_, D_, D_, V_,
                   false, false, false, lsp, 1, 1, 0,0,0,0,0,0};
        gemm128x128w(g);
    }

    lossrow2_kernel<<<BT_/8, 256>>>(lsp, NCH_, logits, targets, rl);
    if (out_has_logits && (long long)out_size > NLOGITS) {
        lossreduce_kernel<<<1, 256>>>(rl, out + NLOGITS);
    } else if (!out_has_logits && out_size >= 1) {
        lossreduce_kernel<<<1, 256>>>(rl, out);
    }
}